// round 6
// baseline (speedup 1.0000x reference)
#include <cuda_runtime.h>
#include <math.h>
#include <stdint.h>

// ---------------------------------------------------------------------------
// iTransformer encoder, round 6: 3xTF32 tensor-core GEMMs with PRE-SPLIT
// operands (hi/lo packed, smem-permutation baked in), LN fused into split.
// B=16, S=1024, T=512, D=256, H=8, DH=32, L=4, FF=1024. M = B*S = 16384.
// ---------------------------------------------------------------------------

#define M_ROWS 16384
#define D_MODEL 256
#define T_IN 512
#define FF_DIM 1024
#define N_HEADS 8
#define DH 32
#define SEQ 1024
#define N_LAYERS 4

__device__ float g_y[M_ROWS * D_MODEL];       // tokenize output (pre-LN)
__device__ float g_h[M_ROWS * D_MODEL];       // residual stream
__device__ float g_qkv[M_ROWS * 3 * D_MODEL];
__device__ float g_att[M_ROWS * D_MODEL];
__device__ float g_ff[M_ROWS * FF_DIM];
// activation split scratch: up to 16384 rows x (1024/8) slices x 4 float4
__device__ float4 g_asp[M_ROWS * (FF_DIM / 8) * 4];
// weight split storage (all tensors, all layers): 1,638,400 float4 = 26.2MB
#define WOFF_TOK 0
#define WOFF_INPJ 65536
#define WSTR_INPJ 98304   // 768*256/2 per layer
#define WOFF_OUT 458752
#define WSTR_OUT 32768
#define WOFF_L1 589824
#define WSTR_L1 131072
#define WOFF_L2 1114112
#define WSTR_L2 131072
#define WSP_TOTAL 1638400
__device__ float4 g_wsp[WSP_TOTAL];

__device__ __forceinline__ float tf32_round(float x) {
  uint32_t u;
  asm("cvt.rna.tf32.f32 %0, %1;" : "=r"(u) : "f"(x));
  return __uint_as_float(u);
}

__device__ __forceinline__ void mma_tf32(float* d, const uint32_t* a,
                                         const uint32_t* b) {
  asm volatile(
      "mma.sync.aligned.m16n8k8.row.col.f32.tf32.tf32.f32 "
      "{%0,%1,%2,%3}, {%4,%5,%6,%7}, {%8,%9}, {%0,%1,%2,%3};\n"
      : "+f"(d[0]), "+f"(d[1]), "+f"(d[2]), "+f"(d[3])
      : "r"(a[0]), "r"(a[1]), "r"(a[2]), "r"(a[3]), "r"(b[0]), "r"(b[1]));
}

// ---------------------------------------------------------------------------
// Split layout: for X[R][K], S=K/8 slices. At float4 index (r*S+s)*4 + c',
// with c' = c ^ (r&3) ^ ((s&1)<<1), holds
// (hi(X[r][s*8+c]), hi(X[r][s*8+c+4]), lo(X[r][s*8+c]), lo(X[r][s*8+c+4])).
// GEMM copies these verbatim into smem; fragment loads de-permute.
// ---------------------------------------------------------------------------
__global__ __launch_bounds__(256) void split_mat_kernel(
    const float* __restrict__ X, float4* __restrict__ out, int total_slices,
    int S) {
  const int idx = blockIdx.x * 256 + threadIdx.x;
  if (idx >= total_slices) return;
  const int r = idx / S;
  const int s = idx - r * S;
  float4 x0 = *(const float4*)(X + (size_t)idx * 8);
  float4 x1 = *(const float4*)(X + (size_t)idx * 8 + 4);
  float v[8] = {x0.x, x0.y, x0.z, x0.w, x1.x, x1.y, x1.z, x1.w};
  float hi[8], lo[8];
#pragma unroll
  for (int i = 0; i < 8; i++) {
    hi[i] = tf32_round(v[i]);
    lo[i] = tf32_round(v[i] - hi[i]);
  }
  const int prm = (r & 3) ^ ((s & 1) << 1);
  float4* o = out + (size_t)idx * 4;
#pragma unroll
  for (int c = 0; c < 4; c++)
    o[c ^ prm] = make_float4(hi[c], hi[c + 4], lo[c], lo[c + 4]);
}

// ---------------------------------------------------------------------------
// Fused LayerNorm(256) + split. One block per row, 256 threads.
// ---------------------------------------------------------------------------
__global__ __launch_bounds__(256) void ln_split_kernel(
    const float* __restrict__ in, const float* __restrict__ g,
    const float* __restrict__ b, float4* __restrict__ out) {
  const int row = blockIdx.x;
  const int t = threadIdx.x;
  float v = in[(size_t)row * D_MODEL + t];

  float s = v;
#pragma unroll
  for (int o = 16; o > 0; o >>= 1) s += __shfl_xor_sync(0xffffffffu, s, o);
  __shared__ float ws[8];
  __shared__ float ws2[8];
  if ((t & 31) == 0) ws[t >> 5] = s;
  __syncthreads();
  float mean = (ws[0] + ws[1] + ws[2] + ws[3] + ws[4] + ws[5] + ws[6] + ws[7]) *
               (1.0f / 256.0f);
  float d = v - mean;
  float s2 = d * d;
#pragma unroll
  for (int o = 16; o > 0; o >>= 1) s2 += __shfl_xor_sync(0xffffffffu, s2, o);
  if ((t & 31) == 0) ws2[t >> 5] = s2;
  __syncthreads();
  float var = (ws2[0] + ws2[1] + ws2[2] + ws2[3] + ws2[4] + ws2[5] + ws2[6] +
               ws2[7]) * (1.0f / 256.0f);
  float vn = d * rsqrtf(var + 1e-5f) * g[t] + b[t];

  float hi = tf32_round(vn);
  float lo = tf32_round(vn - hi);
  float hip = __shfl_xor_sync(0xffffffffu, hi, 4);
  float lop = __shfl_xor_sync(0xffffffffu, lo, 4);
  const int tl = t & 7;
  if (tl < 4) {
    const int sl = t >> 3;  // slice 0..31
    const int cp = tl ^ (row & 3) ^ ((sl & 1) << 1);
    out[((size_t)row * 32 + sl) * 4 + cp] = make_float4(hi, hip, lo, lop);
  }
}

// ---------------------------------------------------------------------------
// 3xTF32 GEMM on pre-split operands.
// C[M,N] = A[M,K] @ B[N,K]^T + bias[N] (+ReLU) (+residual)
// Block 128x128xK16, 8 warps (2x4), warp tile 64x32, mma m16n8k8.
// Dynamic smem 64KB, double-buffered. M%128==0, N%128==0, K%16==0.
// ---------------------------------------------------------------------------
#define AS(buf, s, row, c) AsP[((((buf)*2 + (s)) * 128 + (row)) << 2) + (c)]
#define BS(buf, s, row, c) BsP[((((buf)*2 + (s)) * 128 + (row)) << 2) + (c)]
#define GEMM_SMEM_BYTES (2 * 2 * 128 * 4 * 16 * 2)

#define STAGE_STORE(BUF, OFF)                                                  \
  do {                                                                         \
    float4 a0 = Ap[(OFF) + 0], a1 = Ap[(OFF) + 1];                             \
    float4 a2 = Ap[(OFF) + 2], a3 = Ap[(OFF) + 3];                             \
    float4 b0 = Bp[(OFF) + 0], b1 = Bp[(OFF) + 1];                             \
    float4 b2 = Bp[(OFF) + 2], b3 = Bp[(OFF) + 3];                             \
    AS(BUF, lsl, lrow, 0) = a0; AS(BUF, lsl, lrow, 1) = a1;                    \
    AS(BUF, lsl, lrow, 2) = a2; AS(BUF, lsl, lrow, 3) = a3;                    \
    BS(BUF, lsl, lrow, 0) = b0; BS(BUF, lsl, lrow, 1) = b1;                    \
    BS(BUF, lsl, lrow, 2) = b2; BS(BUF, lsl, lrow, 3) = b3;                    \
  } while (0)

#define COMPUTE_STAGE(BUF)                                                     \
  _Pragma("unroll") for (int s = 0; s < 2; s++) {                              \
    uint32_t bfH[4][2], bfL[4][2];                                             \
    _Pragma("unroll") for (int nt = 0; nt < 4; nt++) {                         \
      const int row = wn * 32 + nt * 8 + gid;                                  \
      float4 pb = BS(BUF, s, row, tg ^ (row & 3) ^ (s << 1));                  \
      bfH[nt][0] = __float_as_uint(pb.x); bfH[nt][1] = __float_as_uint(pb.y);  \
      bfL[nt][0] = __float_as_uint(pb.z); bfL[nt][1] = __float_as_uint(pb.w);  \
    }                                                                          \
    _Pragma("unroll") for (int mt = 0; mt < 4; mt++) {                         \
      const int rb = wm * 64 + mt * 16 + gid;                                  \
      const int pc = tg ^ (rb & 3) ^ (s << 1);                                 \
      float4 p0 = AS(BUF, s, rb, pc);                                          \
      float4 p8 = AS(BUF, s, rb + 8, pc);                                      \
      uint32_t afH[4] = {__float_as_uint(p0.x), __float_as_uint(p8.x),         \
                         __float_as_uint(p0.y), __float_as_uint(p8.y)};        \
      uint32_t afL[4] = {__float_as_uint(p0.z), __float_as_uint(p8.z),         \
                         __float_as_uint(p0.w), __float_as_uint(p8.w)};        \
      _Pragma("unroll") for (int nt = 0; nt < 4; nt++) {                       \
        mma_tf32(acc[mt][nt], afH, bfH[nt]);                                   \
        mma_tf32(acc[mt][nt], afH, bfL[nt]);                                   \
        mma_tf32(acc[mt][nt], afL, bfH[nt]);                                   \
      }                                                                        \
    }                                                                          \
  }

template <bool RELU, bool RES>
__global__ __launch_bounds__(256, 2) void gemm_sp_kernel(
    const float4* __restrict__ A4, const float4* __restrict__ B4,
    const float* __restrict__ bias, const float* __restrict__ res,
    float* __restrict__ C, int M, int N, int K) {
  extern __shared__ float4 smem_dyn[];
  float4* AsP = smem_dyn;
  float4* BsP = smem_dyn + 2 * 2 * 128 * 4;

  const int tid = threadIdx.x;
  const int lane = tid & 31;
  const int warp = tid >> 5;
  const int wm = warp >> 2;
  const int wn = warp & 3;
  const int gid = lane >> 2;
  const int tg = lane & 3;

  const int m0 = blockIdx.y * 128;
  const int n0 = blockIdx.x * 128;

  const int lrow = tid >> 1;     // 0..127
  const int lsl = tid & 1;       // k-slice 0/1 within 16-k tile

  const int S4 = K >> 1;         // row stride in float4
  const float4* Ap = A4 + (size_t)(m0 + lrow) * S4 + lsl * 4;
  const float4* Bp = B4 + (size_t)(n0 + lrow) * S4 + lsl * 4;

  float acc[4][4][4];
#pragma unroll
  for (int i = 0; i < 4; i++)
#pragma unroll
    for (int j = 0; j < 4; j++)
#pragma unroll
      for (int r = 0; r < 4; r++) acc[i][j][r] = 0.f;

  STAGE_STORE(0, 0);
  __syncthreads();

  int buf = 0;
  for (int k0 = 16; k0 < K; k0 += 16) {
    const int off = k0 >> 1;
    COMPUTE_STAGE(buf);
    const int nxt = buf ^ 1;
    STAGE_STORE(nxt, off);
    __syncthreads();
    buf = nxt;
  }
  COMPUTE_STAGE(buf);

#pragma unroll
  for (int mt = 0; mt < 4; mt++) {
    const int row = m0 + wm * 64 + mt * 16 + gid;
#pragma unroll
    for (int nt = 0; nt < 4; nt++) {
      const int col = n0 + wn * 32 + nt * 8 + tg * 2;
      float2 bb = *(const float2*)&bias[col];
      float2 r0 = make_float2(acc[mt][nt][0] + bb.x, acc[mt][nt][1] + bb.y);
      float2 r1 = make_float2(acc[mt][nt][2] + bb.x, acc[mt][nt][3] + bb.y);
      if (RELU) {
        r0.x = fmaxf(r0.x, 0.f); r0.y = fmaxf(r0.y, 0.f);
        r1.x = fmaxf(r1.x, 0.f); r1.y = fmaxf(r1.y, 0.f);
      }
      if (RES) {
        float2 q0 = *(const float2*)&res[(size_t)row * N + col];
        float2 q1 = *(const float2*)&res[(size_t)(row + 8) * N + col];
        r0.x += q0.x; r0.y += q0.y;
        r1.x += q1.x; r1.y += q1.y;
      }
      *(float2*)&C[(size_t)row * N + col] = r0;
      *(float2*)&C[(size_t)(row + 8) * N + col] = r1;
    }
  }
}

// ---------------------------------------------------------------------------
// Plain LayerNorm (for tnorm and final norm).
// ---------------------------------------------------------------------------
__global__ __launch_bounds__(256) void ln_kernel(
    const float* __restrict__ in, const float* __restrict__ g,
    const float* __restrict__ b, float* __restrict__ out) {
  const int row = blockIdx.x;
  const int t = threadIdx.x;
  float v = in[(size_t)row * D_MODEL + t];

  float s = v;
#pragma unroll
  for (int o = 16; o > 0; o >>= 1) s += __shfl_xor_sync(0xffffffffu, s, o);
  __shared__ float ws[8];
  __shared__ float ws2[8];
  if ((t & 31) == 0) ws[t >> 5] = s;
  __syncthreads();
  float mean = (ws[0] + ws[1] + ws[2] + ws[3] + ws[4] + ws[5] + ws[6] + ws[7]) *
               (1.0f / 256.0f);
  float d = v - mean;
  float s2 = d * d;
#pragma unroll
  for (int o = 16; o > 0; o >>= 1) s2 += __shfl_xor_sync(0xffffffffu, s2, o);
  if ((t & 31) == 0) ws2[t >> 5] = s2;
  __syncthreads();
  float var = (ws2[0] + ws2[1] + ws2[2] + ws2[3] + ws2[4] + ws2[5] + ws2[6] +
               ws2[7]) * (1.0f / 256.0f);
  out[(size_t)row * D_MODEL + t] = d * rsqrtf(var + 1e-5f) * g[t] + b[t];
}

// ---------------------------------------------------------------------------
// RoPE in-place on q,k of qkv.
// ---------------------------------------------------------------------------
__global__ __launch_bounds__(256) void rope_kernel(float* __restrict__ qkv) {
  int idx = blockIdx.x * 256 + threadIdx.x;  // M_ROWS * 8 * 16
  int j = idx & 15;
  int h = (idx >> 4) & 7;
  int row = idx >> 7;
  int s = row & (SEQ - 1);
  float inv_freq = 1.0f / powf(10000.0f, (float)j * 0.0625f);
  float freq = (float)s * inv_freq;
  float c, sn;
  sincosf(freq, &c, &sn);
  size_t base = (size_t)row * 768 + h * 32 + j;
  float q1 = qkv[base], q2 = qkv[base + 16];
  qkv[base]      = q1 * c - q2 * sn;
  qkv[base + 16] = q2 * c + q1 * sn;
  float k1 = qkv[base + 256], k2 = qkv[base + 272];
  qkv[base + 256] = k1 * c - k2 * sn;
  qkv[base + 272] = k2 * c + k1 * sn;
}

// ---------------------------------------------------------------------------
// Flash attention, fp32 (R4 version). Grid (S/64, B*H), 256 threads.
// ---------------------------------------------------------------------------
#define BQ 64
#define BKT 64
__global__ __launch_bounds__(256) void attn_kernel(
    const float* __restrict__ qkv, float* __restrict__ out) {
  __shared__ float Qt[DH][BQ];
  __shared__ float Kt[DH][BKT];
  __shared__ float Vs[BKT][36];
  __shared__ float Ps[BKT][68];

  const int tid = threadIdx.x;
  const int bh = blockIdx.y;
  const int b = bh >> 3;
  const int h = bh & 7;
  const int q0 = blockIdx.x * BQ;
  const float scale = 0.17677669529663687f;

  const int lr = tid & 63;
  const int lds = tid >> 6;
  const int r64 = tid >> 2;
  const int dc = (tid & 3) << 3;

  const int tx = tid & 15;
  const int ty = tid >> 4;
  const int jh = tx >> 3;
  const int dm = tx & 7;

  {
    const float* qb = qkv + (size_t)(b * SEQ + q0 + lr) * 768 + h * 32 + lds * 8;
#pragma unroll
    for (int i = 0; i < 8; i++) Qt[lds * 8 + i][lr] = qb[i] * scale;
  }

  float m_i[4], l_i[4];
#pragma unroll
  for (int i = 0; i < 4; i++) { m_i[i] = -INFINITY; l_i[i] = 0.f; }
  float O[4][4];
#pragma unroll
  for (int i = 0; i < 4; i++)
#pragma unroll
    for (int d = 0; d < 4; d++) O[i][d] = 0.f;

  for (int kt = 0; kt < SEQ / BKT; kt++) {
    const int k0 = kt * BKT;
    __syncthreads();
    {
      const float* kb =
          qkv + (size_t)(b * SEQ + k0 + lr) * 768 + 256 + h * 32 + lds * 8;
#pragma unroll
      for (int i = 0; i < 8; i++) Kt[lds * 8 + i][lr] = kb[i];
      const float* vb =
          qkv + (size_t)(b * SEQ + k0 + r64) * 768 + 512 + h * 32 + dc;
      *(float4*)&Vs[r64][dc] = *(const float4*)vb;
      *(float4*)&Vs[r64][dc + 4] = *(const float4*)(vb + 4);
    }
    __syncthreads();

    float s4[4][4];
#pragma unroll
    for (int i = 0; i < 4; i++)
#pragma unroll
      for (int j = 0; j < 4; j++) s4[i][j] = 0.f;
#pragma unroll
    for (int d = 0; d < DH; d++) {
      float4 qv = *(const float4*)&Qt[d][ty * 4];
      float4 kv = *(const float4*)&Kt[d][tx * 4];
      float qa[4] = {qv.x, qv.y, qv.z, qv.w};
      float ka[4] = {kv.x, kv.y, kv.z, kv.w};
#pragma unroll
      for (int i = 0; i < 4; i++)
#pragma unroll
        for (int j = 0; j < 4; j++) s4[i][j] = fmaf(qa[i], ka[j], s4[i][j]);
    }

    const int swz = (ty ^ (tx >> 1)) * 4;
    float cf_i[4];
#pragma unroll
    for (int i = 0; i < 4; i++) {
      float lm = fmaxf(fmaxf(s4[i][0], s4[i][1]), fmaxf(s4[i][2], s4[i][3]));
#pragma unroll
      for (int o = 8; o > 0; o >>= 1)
        lm = fmaxf(lm, __shfl_xor_sync(0xffffffffu, lm, o));
      float mn = fmaxf(m_i[i], lm);
      cf_i[i] = __expf(m_i[i] - mn);
      m_i[i] = mn;
      float ps = 0.f;
#pragma unroll
      for (int j = 0; j < 4; j++) {
        float p = __expf(s4[i][j] - mn);
        Ps[tx * 4 + j][swz + i] = p;
        ps += p;
      }
#pragma unroll
      for (int o = 8; o > 0; o >>= 1)
        ps += __shfl_xor_sync(0xffffffffu, ps, o);
      l_i[i] = l_i[i] * cf_i[i] + ps;
    }
#pragma unroll
    for (int i = 0; i < 4; i++)
#pragma unroll
      for (int d = 0; d < 4; d++) O[i][d] *= cf_i[i];
    __syncthreads();

#pragma unroll
    for (int jblk = 0; jblk < 4; jblk++) {
      const int c4 = (ty ^ ((jh * 4 + jblk) & 7)) * 4;
#pragma unroll
      for (int jj = 0; jj < 8; jj++) {
        const int j = jh * 32 + jblk * 8 + jj;
        float4 p4 = *(const float4*)&Ps[j][c4];
        float4 v4 = *(const float4*)&Vs[j][dm * 4];
        float pa[4] = {p4.x, p4.y, p4.z, p4.w};
        float va[4] = {v4.x, v4.y, v4.z, v4.w};
#pragma unroll
        for (int i = 0; i < 4; i++)
#pragma unroll
          for (int d = 0; d < 4; d++)
            O[i][d] = fmaf(pa[i], va[d], O[i][d]);
      }
    }
  }

#pragma unroll
  for (int i = 0; i < 4; i++)
#pragma unroll
    for (int d = 0; d < 4; d++)
      O[i][d] += __shfl_xor_sync(0xffffffffu, O[i][d], 8);

  if (jh == 0) {
#pragma unroll
    for (int i = 0; i < 4; i++) {
      const float inv = 1.0f / l_i[i];
      float4 r = make_float4(O[i][0] * inv, O[i][1] * inv, O[i][2] * inv,
                             O[i][3] * inv);
      *(float4*)&out[(size_t)(b * SEQ + q0 + ty * 4 + i) * D_MODEL + h * 32 +
                     dm * 4] = r;
    }
  }
}

// ---------------------------------------------------------------------------
// Launch
// ---------------------------------------------------------------------------
extern "C" void kernel_launch(void* const* d_in, const int* in_sizes, int n_in,
                              void* d_out, int out_size) {
  const float* x         = (const float*)d_in[0];
  const float* tok_w     = (const float*)d_in[1];
  const float* tok_b     = (const float*)d_in[2];
  const float* tnorm_g   = (const float*)d_in[3];
  const float* tnorm_b   = (const float*)d_in[4];
  const float* in_proj_w = (const float*)d_in[5];
  const float* in_proj_b = (const float*)d_in[6];
  const float* out_w     = (const float*)d_in[7];
  const float* out_b     = (const float*)d_in[8];
  const float* ln1_g     = (const float*)d_in[9];
  const float* ln1_b     = (const float*)d_in[10];
  const float* ln2_g     = (const float*)d_in[11];
  const float* ln2_b     = (const float*)d_in[12];
  const float* lin1_w    = (const float*)d_in[13];
  const float* lin1_b    = (const float*)d_in[14];
  const float* lin2_w    = (const float*)d_in[15];
  const float* lin2_b    = (const float*)d_in[16];
  const float* fnorm_g   = (const float*)d_in[17];
  const float* fnorm_b   = (const float*)d_in[18];
  float* out = (float*)d_out;

  float *y, *h, *qkv, *att, *ff;
  float4 *asp, *wsp;
  cudaGetSymbolAddress((void**)&y, g_y);
  cudaGetSymbolAddress((void**)&h, g_h);
  cudaGetSymbolAddress((void**)&qkv, g_qkv);
  cudaGetSymbolAddress((void**)&att, g_att);
  cudaGetSymbolAddress((void**)&ff, g_ff);
  cudaGetSymbolAddress((void**)&asp, g_asp);
  cudaGetSymbolAddress((void**)&wsp, g_wsp);

  const int M = M_ROWS;
  const int SB = GEMM_SMEM_BYTES;
  cudaFuncSetAttribute(gemm_sp_kernel<false, false>,
                       cudaFuncAttributeMaxDynamicSharedMemorySize, SB);
  cudaFuncSetAttribute(gemm_sp_kernel<false, true>,
                       cudaFuncAttributeMaxDynamicSharedMemorySize, SB);
  cudaFuncSetAttribute(gemm_sp_kernel<true, false>,
                       cudaFuncAttributeMaxDynamicSharedMemorySize, SB);

  dim3 blk(256);
#define SPLIT(SRC, DST, R, K)                                            \
  split_mat_kernel<<<((R) * ((K) / 8) + 255) / 256, blk>>>(              \
      SRC, DST, (R) * ((K) / 8), (K) / 8)

  // Weight splits (per launch; deterministic).
  SPLIT(tok_w, wsp + WOFF_TOK, 256, 512);
  SPLIT(in_proj_w, wsp + WOFF_INPJ, 4 * 768, 256);
  SPLIT(out_w, wsp + WOFF_OUT, 4 * 256, 256);
  SPLIT(lin1_w, wsp + WOFF_L1, 4 * 1024, 256);
  SPLIT(lin2_w, wsp + WOFF_L2, 4 * 256, 1024);

  // Tokenize
  SPLIT(x, asp, M, 512);
  gemm_sp_kernel<false, false><<<dim3(2, M / 128), blk, SB>>>(
      asp, wsp + WOFF_TOK, tok_b, nullptr, y, M, D_MODEL, T_IN);
  ln_kernel<<<M, blk>>>(y, tnorm_g, tnorm_b, h);

  for (int i = 0; i < N_LAYERS; i++) {
    ln_split_kernel<<<M, blk>>>(h, ln1_g + i * D_MODEL, ln1_b + i * D_MODEL,
                                asp);
    gemm_sp_kernel<false, false><<<dim3(6, M / 128), blk, SB>>>(
        asp, wsp + WOFF_INPJ + (size_t)i * WSTR_INPJ, in_proj_b + i * 768,
        nullptr, qkv, M, 768, D_MODEL);
    rope_kernel<<<(M_ROWS * 128) / 256, blk>>>(qkv);
    attn_kernel<<<dim3(SEQ / BQ, 16 * N_HEADS), blk>>>(qkv, att);
    SPLIT(att, asp, M, 256);
    gemm_sp_kernel<false, true><<<dim3(2, M / 128), blk, SB>>>(
        asp, wsp + WOFF_OUT + (size_t)i * WSTR_OUT, out_b + i * D_MODEL, h, h,
        M, D_MODEL, D_MODEL);
    ln_split_kernel<<<M, blk>>>(h, ln2_g + i * D_MODEL, ln2_b + i * D_MODEL,
                                asp);
    gemm_sp_kernel<true, false><<<dim3(8, M / 128), blk, SB>>>(
        asp, wsp + WOFF_L1 + (size_t)i * WSTR_L1, lin1_b + i * FF_DIM, nullptr,
        ff, M, FF_DIM, D_MODEL);
    SPLIT(ff, asp, M, 1024);
    gemm_sp_kernel<false, true><<<dim3(2, M / 128), blk, SB>>>(
        asp, wsp + WOFF_L2 + (size_t)i * WSTR_L2, lin2_b + i * D_MODEL, h, h,
        M, D_MODEL, FF_DIM);
  }

  ln_kernel<<<M, blk>>>(h, fnorm_g, fnorm_b, out);
}

// round 7
// speedup vs baseline: 1.0114x; 1.0114x over previous
#include <cuda_runtime.h>
#include <math.h>
#include <stdint.h>

// ---------------------------------------------------------------------------
// iTransformer encoder, round 7: 3xTF32 pre-split GEMMs with splits FUSED
// into producers (LN-split, attn-epilogue-split, lin1-epilogue-split).
// B=16, S=1024, T=512, D=256, H=8, DH=32, L=4, FF=1024. M = B*S = 16384.
// ---------------------------------------------------------------------------

#define M_ROWS 16384
#define D_MODEL 256
#define T_IN 512
#define FF_DIM 1024
#define N_HEADS 8
#define DH 32
#define SEQ 1024
#define N_LAYERS 4

__device__ float g_y[M_ROWS * D_MODEL];
__device__ float g_h[M_ROWS * D_MODEL];
__device__ float g_qkv[M_ROWS * 3 * D_MODEL];
__device__ float g_rope_c[SEQ * 16];
__device__ float g_rope_s[SEQ * 16];
// split activations: A-region (x / ln / att splits; up to 64 slices/row),
// B-region (ff split; 128 slices/row)
__device__ float4 g_aspA[M_ROWS * 64 * 4];
__device__ float4 g_aspB[M_ROWS * 128 * 4];
// weight split storage
#define WOFF_TOK 0
#define WOFF_INPJ 65536
#define WSTR_INPJ 98304
#define WOFF_OUT 458752
#define WSTR_OUT 32768
#define WOFF_L1 589824
#define WSTR_L1 131072
#define WOFF_L2 1114112
#define WSTR_L2 131072
#define WSP_TOTAL 1638400
__device__ float4 g_wsp[WSP_TOTAL];

__device__ __forceinline__ float tf32_round(float x) {
  uint32_t u;
  asm("cvt.rna.tf32.f32 %0, %1;" : "=r"(u) : "f"(x));
  return __uint_as_float(u);
}

__device__ __forceinline__ void mma_tf32(float* d, const uint32_t* a,
                                         const uint32_t* b) {
  asm volatile(
      "mma.sync.aligned.m16n8k8.row.col.f32.tf32.tf32.f32 "
      "{%0,%1,%2,%3}, {%4,%5,%6,%7}, {%8,%9}, {%0,%1,%2,%3};\n"
      : "+f"(d[0]), "+f"(d[1]), "+f"(d[2]), "+f"(d[3])
      : "r"(a[0]), "r"(a[1]), "r"(a[2]), "r"(a[3]), "r"(b[0]), "r"(b[1]));
}

// ---------------------------------------------------------------------------
// Split layout (same as R6): X[R][K], S=K/8. float4 idx (r*S+s)*4 + c',
// c' = c ^ (r&3) ^ ((s&1)<<1), holds (hi(s8+c), hi(s8+c+4), lo(s8+c), lo(s8+c+4)).
// ---------------------------------------------------------------------------
__global__ __launch_bounds__(256) void split_mat_kernel(
    const float* __restrict__ X, float4* __restrict__ out, int total_slices,
    int S) {
  const int idx = blockIdx.x * 256 + threadIdx.x;
  if (idx >= total_slices) return;
  const int r = idx / S;
  const int s = idx - r * S;
  float4 x0 = *(const float4*)(X + (size_t)idx * 8);
  float4 x1 = *(const float4*)(X + (size_t)idx * 8 + 4);
  float v[8] = {x0.x, x0.y, x0.z, x0.w, x1.x, x1.y, x1.z, x1.w};
  float hi[8], lo[8];
#pragma unroll
  for (int i = 0; i < 8; i++) {
    hi[i] = tf32_round(v[i]);
    lo[i] = tf32_round(v[i] - hi[i]);
  }
  const int prm = (r & 3) ^ ((s & 1) << 1);
  float4* o = out + (size_t)idx * 4;
#pragma unroll
  for (int c = 0; c < 4; c++)
    o[c ^ prm] = make_float4(hi[c], hi[c + 4], lo[c], lo[c + 4]);
}

// ---------------------------------------------------------------------------
// Fused LayerNorm(256) + split (proven R6).
// ---------------------------------------------------------------------------
__global__ __launch_bounds__(256) void ln_split_kernel(
    const float* __restrict__ in, const float* __restrict__ g,
    const float* __restrict__ b, float4* __restrict__ out) {
  const int row = blockIdx.x;
  const int t = threadIdx.x;
  float v = in[(size_t)row * D_MODEL + t];

  float s = v;
#pragma unroll
  for (int o = 16; o > 0; o >>= 1) s += __shfl_xor_sync(0xffffffffu, s, o);
  __shared__ float ws[8];
  __shared__ float ws2[8];
  if ((t & 31) == 0) ws[t >> 5] = s;
  __syncthreads();
  float mean = (ws[0] + ws[1] + ws[2] + ws[3] + ws[4] + ws[5] + ws[6] + ws[7]) *
               (1.0f / 256.0f);
  float d = v - mean;
  float s2 = d * d;
#pragma unroll
  for (int o = 16; o > 0; o >>= 1) s2 += __shfl_xor_sync(0xffffffffu, s2, o);
  if ((t & 31) == 0) ws2[t >> 5] = s2;
  __syncthreads();
  float var = (ws2[0] + ws2[1] + ws2[2] + ws2[3] + ws2[4] + ws2[5] + ws2[6] +
               ws2[7]) * (1.0f / 256.0f);
  float vn = d * rsqrtf(var + 1e-5f) * g[t] + b[t];

  float hi = tf32_round(vn);
  float lo = tf32_round(vn - hi);
  float hip = __shfl_xor_sync(0xffffffffu, hi, 4);
  float lop = __shfl_xor_sync(0xffffffffu, lo, 4);
  const int tl = t & 7;
  if (tl < 4) {
    const int sl = t >> 3;
    const int cp = tl ^ (row & 3) ^ ((sl & 1) << 1);
    out[((size_t)row * 32 + sl) * 4 + cp] = make_float4(hi, hip, lo, lop);
  }
}

// ---------------------------------------------------------------------------
// 3xTF32 GEMM on pre-split operands (R6, proven). Optional SPLITOUT epilogue
// writes the split form of C (for lin1 -> lin2 chaining) instead of raw C.
// ---------------------------------------------------------------------------
#define AS(buf, s, row, c) AsP[((((buf)*2 + (s)) * 128 + (row)) << 2) + (c)]
#define BS(buf, s, row, c) BsP[((((buf)*2 + (s)) * 128 + (row)) << 2) + (c)]
#define GEMM_SMEM_BYTES (2 * 2 * 128 * 4 * 16 * 2)

#define STAGE_STORE(BUF, OFF)                                                  \
  do {                                                                         \
    float4 a0 = Ap[(OFF) + 0], a1 = Ap[(OFF) + 1];                             \
    float4 a2 = Ap[(OFF) + 2], a3 = Ap[(OFF) + 3];                             \
    float4 b0 = Bp[(OFF) + 0], b1 = Bp[(OFF) + 1];                             \
    float4 b2 = Bp[(OFF) + 2], b3 = Bp[(OFF) + 3];                             \
    AS(BUF, lsl, lrow, 0) = a0; AS(BUF, lsl, lrow, 1) = a1;                    \
    AS(BUF, lsl, lrow, 2) = a2; AS(BUF, lsl, lrow, 3) = a3;                    \
    BS(BUF, lsl, lrow, 0) = b0; BS(BUF, lsl, lrow, 1) = b1;                    \
    BS(BUF, lsl, lrow, 2) = b2; BS(BUF, lsl, lrow, 3) = b3;                    \
  } while (0)

#define COMPUTE_STAGE(BUF)                                                     \
  _Pragma("unroll") for (int s = 0; s < 2; s++) {                              \
    uint32_t bfH[4][2], bfL[4][2];                                             \
    _Pragma("unroll") for (int nt = 0; nt < 4; nt++) {                         \
      const int row = wn * 32 + nt * 8 + gid;                                  \
      float4 pb = BS(BUF, s, row, tg ^ (row & 3) ^ (s << 1));                  \
      bfH[nt][0] = __float_as_uint(pb.x); bfH[nt][1] = __float_as_uint(pb.y);  \
      bfL[nt][0] = __float_as_uint(pb.z); bfL[nt][1] = __float_as_uint(pb.w);  \
    }                                                                          \
    _Pragma("unroll") for (int mt = 0; mt < 4; mt++) {                         \
      const int rb = wm * 64 + mt * 16 + gid;                                  \
      const int pc = tg ^ (rb & 3) ^ (s << 1);                                 \
      float4 p0 = AS(BUF, s, rb, pc);                                          \
      float4 p8 = AS(BUF, s, rb + 8, pc);                                      \
      uint32_t afH[4] = {__float_as_uint(p0.x), __float_as_uint(p8.x),         \
                         __float_as_uint(p0.y), __float_as_uint(p8.y)};        \
      uint32_t afL[4] = {__float_as_uint(p0.z), __float_as_uint(p8.z),         \
                         __float_as_uint(p0.w), __float_as_uint(p8.w)};        \
      _Pragma("unroll") for (int nt = 0; nt < 4; nt++) {                       \
        mma_tf32(acc[mt][nt], afH, bfH[nt]);                                   \
        mma_tf32(acc[mt][nt], afH, bfL[nt]);                                   \
        mma_tf32(acc[mt][nt], afL, bfH[nt]);                                   \
      }                                                                        \
    }                                                                          \
  }

template <bool RELU, bool RES, bool SPLITOUT>
__global__ __launch_bounds__(256, 2) void gemm_sp_kernel(
    const float4* __restrict__ A4, const float4* __restrict__ B4,
    const float* __restrict__ bias, const float* __restrict__ res,
    float* __restrict__ C, float4* __restrict__ C4, int M, int N, int K) {
  extern __shared__ float4 smem_dyn[];
  float4* AsP = smem_dyn;
  float4* BsP = smem_dyn + 2 * 2 * 128 * 4;

  const int tid = threadIdx.x;
  const int lane = tid & 31;
  const int warp = tid >> 5;
  const int wm = warp >> 2;
  const int wn = warp & 3;
  const int gid = lane >> 2;
  const int tg = lane & 3;

  const int m0 = blockIdx.y * 128;
  const int n0 = blockIdx.x * 128;

  const int lrow = tid >> 1;
  const int lsl = tid & 1;

  const int S4 = K >> 1;
  const float4* Ap = A4 + (size_t)(m0 + lrow) * S4 + lsl * 4;
  const float4* Bp = B4 + (size_t)(n0 + lrow) * S4 + lsl * 4;

  float acc[4][4][4];
#pragma unroll
  for (int i = 0; i < 4; i++)
#pragma unroll
    for (int j = 0; j < 4; j++)
#pragma unroll
      for (int r = 0; r < 4; r++) acc[i][j][r] = 0.f;

  STAGE_STORE(0, 0);
  __syncthreads();

  int buf = 0;
  for (int k0 = 16; k0 < K; k0 += 16) {
    const int off = k0 >> 1;
    COMPUTE_STAGE(buf);
    const int nxt = buf ^ 1;
    STAGE_STORE(nxt, off);
    __syncthreads();
    buf = nxt;
  }
  COMPUTE_STAGE(buf);

  const int SN = N >> 3;  // slices per output row
#pragma unroll
  for (int mt = 0; mt < 4; mt++) {
    const int row = m0 + wm * 64 + mt * 16 + gid;
#pragma unroll
    for (int nt = 0; nt < 4; nt++) {
      const int colb = n0 + wn * 32 + nt * 8;
      const int col = colb + tg * 2;
      float2 bb = *(const float2*)&bias[col];
      float2 r0 = make_float2(acc[mt][nt][0] + bb.x, acc[mt][nt][1] + bb.y);
      float2 r1 = make_float2(acc[mt][nt][2] + bb.x, acc[mt][nt][3] + bb.y);
      if (RELU) {
        r0.x = fmaxf(r0.x, 0.f); r0.y = fmaxf(r0.y, 0.f);
        r1.x = fmaxf(r1.x, 0.f); r1.y = fmaxf(r1.y, 0.f);
      }
      if (RES) {
        float2 q0 = *(const float2*)&res[(size_t)row * N + col];
        float2 q1 = *(const float2*)&res[(size_t)(row + 8) * N + col];
        r0.x += q0.x; r0.y += q0.y;
        r1.x += q1.x; r1.y += q1.y;
      }
      if (!SPLITOUT) {
        *(float2*)&C[(size_t)row * N + col] = r0;
        *(float2*)&C[(size_t)(row + 8) * N + col] = r1;
      } else {
        // split epilogue: lanes tg & tg^2 jointly cover cols c and c+4
        float h0 = tf32_round(r0.x), h1 = tf32_round(r0.y);
        float l0 = tf32_round(r0.x - h0), l1 = tf32_round(r0.y - h1);
        float g0 = tf32_round(r1.x), g1 = tf32_round(r1.y);
        float m0f = tf32_round(r1.x - g0), m1f = tf32_round(r1.y - g1);
        float ph0 = __shfl_xor_sync(0xffffffffu, h0, 2);
        float ph1 = __shfl_xor_sync(0xffffffffu, h1, 2);
        float pl0 = __shfl_xor_sync(0xffffffffu, l0, 2);
        float pl1 = __shfl_xor_sync(0xffffffffu, l1, 2);
        float pg0 = __shfl_xor_sync(0xffffffffu, g0, 2);
        float pg1 = __shfl_xor_sync(0xffffffffu, g1, 2);
        float pm0 = __shfl_xor_sync(0xffffffffu, m0f, 2);
        float pm1 = __shfl_xor_sync(0xffffffffu, m1f, 2);
        const int sl = colb >> 3;
        if (tg < 2) {  // write row's float4s for c = tg*2, tg*2+1
          const int c0 = tg * 2;
          const int prm = (row & 3) ^ ((sl & 1) << 1);
          float4* o = C4 + ((size_t)row * SN + sl) * 4;
          o[c0 ^ prm] = make_float4(h0, ph0, l0, pl0);
          o[(c0 + 1) ^ prm] = make_float4(h1, ph1, l1, pl1);
        } else {  // write (row+8)'s float4s for c = (tg-2)*2, +1
          const int c0 = (tg - 2) * 2;
          const int rw = row + 8;
          const int prm = (rw & 3) ^ ((sl & 1) << 1);
          float4* o = C4 + ((size_t)rw * SN + sl) * 4;
          o[c0 ^ prm] = make_float4(pg0, g0, pm0, m0f);
          o[(c0 + 1) ^ prm] = make_float4(pg1, g1, pm1, m1f);
        }
      }
    }
  }
}

// ---------------------------------------------------------------------------
// Plain LayerNorm (tnorm + final).
// ---------------------------------------------------------------------------
__global__ __launch_bounds__(256) void ln_kernel(
    const float* __restrict__ in, const float* __restrict__ g,
    const float* __restrict__ b, float* __restrict__ out) {
  const int row = blockIdx.x;
  const int t = threadIdx.x;
  float v = in[(size_t)row * D_MODEL + t];

  float s = v;
#pragma unroll
  for (int o = 16; o > 0; o >>= 1) s += __shfl_xor_sync(0xffffffffu, s, o);
  __shared__ float ws[8];
  __shared__ float ws2[8];
  if ((t & 31) == 0) ws[t >> 5] = s;
  __syncthreads();
  float mean = (ws[0] + ws[1] + ws[2] + ws[3] + ws[4] + ws[5] + ws[6] + ws[7]) *
               (1.0f / 256.0f);
  float d = v - mean;
  float s2 = d * d;
#pragma unroll
  for (int o = 16; o > 0; o >>= 1) s2 += __shfl_xor_sync(0xffffffffu, s2, o);
  if ((t & 31) == 0) ws2[t >> 5] = s2;
  __syncthreads();
  float var = (ws2[0] + ws2[1] + ws2[2] + ws2[3] + ws2[4] + ws2[5] + ws2[6] +
               ws2[7]) * (1.0f / 256.0f);
  out[(size_t)row * D_MODEL + t] = d * rsqrtf(var + 1e-5f) * g[t] + b[t];
}

// ---------------------------------------------------------------------------
// RoPE table (once per launch) + table-driven RoPE.
// ---------------------------------------------------------------------------
__global__ __launch_bounds__(256) void rope_table_kernel(float* __restrict__ ct,
                                                         float* __restrict__ st) {
  int idx = blockIdx.x * 256 + threadIdx.x;  // SEQ*16
  int j = idx & 15;
  int s = idx >> 4;
  float inv_freq = 1.0f / powf(10000.0f, (float)j * 0.0625f);
  float freq = (float)s * inv_freq;
  float c, sn;
  sincosf(freq, &c, &sn);
  ct[idx] = c;
  st[idx] = sn;
}

__global__ __launch_bounds__(256) void rope_kernel(
    float* __restrict__ qkv, const float* __restrict__ ct,
    const float* __restrict__ st) {
  int idx = blockIdx.x * 256 + threadIdx.x;  // M_ROWS * 8 * 16
  int j = idx & 15;
  int h = (idx >> 4) & 7;
  int row = idx >> 7;
  int s = row & (SEQ - 1);
  float c = ct[s * 16 + j];
  float sn = st[s * 16 + j];
  size_t base = (size_t)row * 768 + h * 32 + j;
  float q1 = qkv[base], q2 = qkv[base + 16];
  qkv[base]      = q1 * c - q2 * sn;
  qkv[base + 16] = q2 * c + q1 * sn;
  float k1 = qkv[base + 256], k2 = qkv[base + 272];
  qkv[base + 256] = k1 * c - k2 * sn;
  qkv[base + 272] = k2 * c + k1 * sn;
}

// ---------------------------------------------------------------------------
// Flash attention, fp32, epilogue writes SPLIT att directly.
// Grid (S/64, B*H), 256 threads.
// ---------------------------------------------------------------------------
#define BQ 64
#define BKT 64
__global__ __launch_bounds__(256) void attn_kernel(
    const float* __restrict__ qkv, float4* __restrict__ out4) {
  __shared__ float Qt[DH][BQ];
  __shared__ float Kt[DH][BKT];
  __shared__ float Vs[BKT][36];
  __shared__ float Ps[BKT][68];

  const int tid = threadIdx.x;
  const int bh = blockIdx.y;
  const int b = bh >> 3;
  const int h = bh & 7;
  const int q0 = blockIdx.x * BQ;
  const float scale = 0.17677669529663687f;

  const int lr = tid & 63;
  const int lds = tid >> 6;
  const int r64 = tid >> 2;
  const int dc = (tid & 3) << 3;

  const int tx = tid & 15;
  const int ty = tid >> 4;
  const int jh = tx >> 3;
  const int dm = tx & 7;

  {
    const float* qb = qkv + (size_t)(b * SEQ + q0 + lr) * 768 + h * 32 + lds * 8;
#pragma unroll
    for (int i = 0; i < 8; i++) Qt[lds * 8 + i][lr] = qb[i] * scale;
  }

  float m_i[4], l_i[4];
#pragma unroll
  for (int i = 0; i < 4; i++) { m_i[i] = -INFINITY; l_i[i] = 0.f; }
  float O[4][4];
#pragma unroll
  for (int i = 0; i < 4; i++)
#pragma unroll
    for (int d = 0; d < 4; d++) O[i][d] = 0.f;

  for (int kt = 0; kt < SEQ / BKT; kt++) {
    const int k0 = kt * BKT;
    __syncthreads();
    {
      const float* kb =
          qkv + (size_t)(b * SEQ + k0 + lr) * 768 + 256 + h * 32 + lds * 8;
#pragma unroll
      for (int i = 0; i < 8; i++) Kt[lds * 8 + i][lr] = kb[i];
      const float* vb =
          qkv + (size_t)(b * SEQ + k0 + r64) * 768 + 512 + h * 32 + dc;
      *(float4*)&Vs[r64][dc] = *(const float4*)vb;
      *(float4*)&Vs[r64][dc + 4] = *(const float4*)(vb + 4);
    }
    __syncthreads();

    float s4[4][4];
#pragma unroll
    for (int i = 0; i < 4; i++)
#pragma unroll
      for (int j = 0; j < 4; j++) s4[i][j] = 0.f;
#pragma unroll
    for (int d = 0; d < DH; d++) {
      float4 qv = *(const float4*)&Qt[d][ty * 4];
      float4 kv = *(const float4*)&Kt[d][tx * 4];
      float qa[4] = {qv.x, qv.y, qv.z, qv.w};
      float ka[4] = {kv.x, kv.y, kv.z, kv.w};
#pragma unroll
      for (int i = 0; i < 4; i++)
#pragma unroll
        for (int j = 0; j < 4; j++) s4[i][j] = fmaf(qa[i], ka[j], s4[i][j]);
    }

    const int swz = (ty ^ (tx >> 1)) * 4;
    float cf_i[4];
#pragma unroll
    for (int i = 0; i < 4; i++) {
      float lm = fmaxf(fmaxf(s4[i][0], s4[i][1]), fmaxf(s4[i][2], s4[i][3]));
#pragma unroll
      for (int o = 8; o > 0; o >>= 1)
        lm = fmaxf(lm, __shfl_xor_sync(0xffffffffu, lm, o));
      float mn = fmaxf(m_i[i], lm);
      cf_i[i] = __expf(m_i[i] - mn);
      m_i[i] = mn;
      float ps = 0.f;
#pragma unroll
      for (int j = 0; j < 4; j++) {
        float p = __expf(s4[i][j] - mn);
        Ps[tx * 4 + j][swz + i] = p;
        ps += p;
      }
#pragma unroll
      for (int o = 8; o > 0; o >>= 1)
        ps += __shfl_xor_sync(0xffffffffu, ps, o);
      l_i[i] = l_i[i] * cf_i[i] + ps;
    }
#pragma unroll
    for (int i = 0; i < 4; i++)
#pragma unroll
      for (int d = 0; d < 4; d++) O[i][d] *= cf_i[i];
    __syncthreads();

#pragma unroll
    for (int jblk = 0; jblk < 4; jblk++) {
      const int c4 = (ty ^ ((jh * 4 + jblk) & 7)) * 4;
#pragma unroll
      for (int jj = 0; jj < 8; jj++) {
        const int j = jh * 32 + jblk * 8 + jj;
        float4 p4 = *(const float4*)&Ps[j][c4];
        float4 v4 = *(const float4*)&Vs[j][dm * 4];
        float pa[4] = {p4.x, p4.y, p4.z, p4.w};
        float va[4] = {v4.x, v4.y, v4.z, v4.w};
#pragma unroll
        for (int i = 0; i < 4; i++)
#pragma unroll
          for (int d = 0; d < 4; d++)
            O[i][d] = fmaf(pa[i], va[d], O[i][d]);
      }
    }
  }

#pragma unroll
  for (int i = 0; i < 4; i++)
#pragma unroll
    for (int d = 0; d < 4; d++)
      O[i][d] += __shfl_xor_sync(0xffffffffu, O[i][d], 8);

  // Split epilogue: cols h*32 + dm*4 + {0..3}; slice = h*4 + dm/2,
  // c = (dm&1)*4 + e. Pair lanes dm, dm^1 to assemble (c, c+4).
  const int sl = h * 4 + (dm >> 1);
#pragma unroll
  for (int i = 0; i < 4; i++) {
    const float inv = 1.0f / l_i[i];
    float hi[4], lo[4];
#pragma unroll
    for (int e = 0; e < 4; e++) {
      float v = O[i][e] * inv;
      hi[e] = tf32_round(v);
      lo[e] = tf32_round(v - hi[e]);
    }
    float phi[4], plo[4];
#pragma unroll
    for (int e = 0; e < 4; e++) {
      phi[e] = __shfl_xor_sync(0xffffffffu, hi[e], 1);
      plo[e] = __shfl_xor_sync(0xffffffffu, lo[e], 1);
    }
    if (jh == 0) {
      const int row = b * SEQ + q0 + ty * 4 + i;
      const int prm = (row & 3) ^ ((sl & 1) << 1);
      float4* o = out4 + ((size_t)row * 32 + sl) * 4;
      const int cw0 = (dm & 1) * 2;
#pragma unroll
      for (int e = 0; e < 2; e++) {
        const int cw = cw0 + e;
        float4 f4;
        if ((dm & 1) == 0)
          f4 = make_float4(hi[cw], phi[cw], lo[cw], plo[cw]);
        else
          f4 = make_float4(phi[cw], hi[cw], plo[cw], lo[cw]);
        o[cw ^ prm] = f4;
      }
    }
  }
}

// ---------------------------------------------------------------------------
// Launch
// ---------------------------------------------------------------------------
extern "C" void kernel_launch(void* const* d_in, const int* in_sizes, int n_in,
                              void* d_out, int out_size) {
  const float* x         = (const float*)d_in[0];
  const float* tok_w     = (const float*)d_in[1];
  const float* tok_b     = (const float*)d_in[2];
  const float* tnorm_g   = (const float*)d_in[3];
  const float* tnorm_b   = (const float*)d_in[4];
  const float* in_proj_w = (const float*)d_in[5];
  const float* in_proj_b = (const float*)d_in[6];
  const float* out_w     = (const float*)d_in[7];
  const float* out_b     = (const float*)d_in[8];
  const float* ln1_g     = (const float*)d_in[9];
  const float* ln1_b     = (const float*)d_in[10];
  const float* ln2_g     = (const float*)d_in[11];
  const float* ln2_b     = (const float*)d_in[12];
  const float* lin1_w    = (const float*)d_in[13];
  const float* lin1_b    = (const float*)d_in[14];
  const float* lin2_w    = (const float*)d_in[15];
  const float* lin2_b    = (const float*)d_in[16];
  const float* fnorm_g   = (const float*)d_in[17];
  const float* fnorm_b   = (const float*)d_in[18];
  float* out = (float*)d_out;

  float *y, *h, *qkv, *rc, *rs;
  float4 *aspA, *aspB, *wsp;
  cudaGetSymbolAddress((void**)&y, g_y);
  cudaGetSymbolAddress((void**)&h, g_h);
  cudaGetSymbolAddress((void**)&qkv, g_qkv);
  cudaGetSymbolAddress((void**)&rc, g_rope_c);
  cudaGetSymbolAddress((void**)&rs, g_rope_s);
  cudaGetSymbolAddress((void**)&aspA, g_aspA);
  cudaGetSymbolAddress((void**)&aspB, g_aspB);
  cudaGetSymbolAddress((void**)&wsp, g_wsp);

  const int M = M_ROWS;
  const int SB = GEMM_SMEM_BYTES;
  cudaFuncSetAttribute(gemm_sp_kernel<false, false, false>,
                       cudaFuncAttributeMaxDynamicSharedMemorySize, SB);
  cudaFuncSetAttribute(gemm_sp_kernel<false, true, false>,
                       cudaFuncAttributeMaxDynamicSharedMemorySize, SB);
  cudaFuncSetAttribute(gemm_sp_kernel<true, false, true>,
                       cudaFuncAttributeMaxDynamicSharedMemorySize, SB);

  dim3 blk(256);
#define SPLIT(SRC, DST, R, K)                                            \
  split_mat_kernel<<<((R) * ((K) / 8) + 255) / 256, blk>>>(              \
      SRC, DST, (R) * ((K) / 8), (K) / 8)

  // Weight splits + rope table (cheap, once per launch).
  SPLIT(tok_w, wsp + WOFF_TOK, 256, 512);
  SPLIT(in_proj_w, wsp + WOFF_INPJ, 4 * 768, 256);
  SPLIT(out_w, wsp + WOFF_OUT, 4 * 256, 256);
  SPLIT(lin1_w, wsp + WOFF_L1, 4 * 1024, 256);
  SPLIT(lin2_w, wsp + WOFF_L2, 4 * 256, 1024);
  rope_table_kernel<<<SEQ * 16 / 256, blk>>>(rc, rs);

  // Tokenize
  SPLIT(x, aspA, M, 512);
  gemm_sp_kernel<false, false, false><<<dim3(2, M / 128), blk, SB>>>(
      aspA, wsp + WOFF_TOK, tok_b, nullptr, y, nullptr, M, D_MODEL, T_IN);
  ln_kernel<<<M, blk>>>(y, tnorm_g, tnorm_b, h);

  for (int i = 0; i < N_LAYERS; i++) {
    ln_split_kernel<<<M, blk>>>(h, ln1_g + i * D_MODEL, ln1_b + i * D_MODEL,
                                aspA);
    gemm_sp_kernel<false, false, false><<<dim3(6, M / 128), blk, SB>>>(
        aspA, wsp + WOFF_INPJ + (size_t)i * WSTR_INPJ, in_proj_b + i * 768,
        nullptr, qkv, nullptr, M, 768, D_MODEL);
    rope_kernel<<<(M_ROWS * 128) / 256, blk>>>(qkv, rc, rs);
    attn_kernel<<<dim3(SEQ / BQ, 16 * N_HEADS), blk>>>(qkv, aspA);
    gemm_sp_kernel<false, true, false><<<dim3(2, M / 128), blk, SB>>>(
        aspA, wsp + WOFF_OUT + (size_t)i * WSTR_OUT, out_b + i * D_MODEL, h, h,
        nullptr, M, D_MODEL, D_MODEL);
    ln_split_kernel<<<M, blk>>>(h, ln2_g + i * D_MODEL, ln2_b + i * D_MODEL,
                                aspA);
    gemm_sp_kernel<true, false, true><<<dim3(8, M / 128), blk, SB>>>(
        aspA, wsp + WOFF_L1 + (size_t)i * WSTR_L1, lin1_b + i * FF_DIM, nullptr,
        nullptr, aspB, M, FF_DIM, D_MODEL);
    gemm_sp_kernel<false, true, false><<<dim3(2, M / 128), blk, SB>>>(
        aspB, wsp + WOFF_L2 + (size_t)i * WSTR_L2, lin2_b + i * D_MODEL, h, h,
        nullptr, M, D_MODEL, FF_DIM);
  }

  ln_kernel<<<M, blk>>>(h, fnorm_g, fnorm_b, out);
}

// round 8
// speedup vs baseline: 1.1939x; 1.1804x over previous
#include <cuda_runtime.h>
#include <math.h>
#include <stdint.h>

// ---------------------------------------------------------------------------
// iTransformer encoder, round 8: R5's in-loop 3xTF32 GEMM core (proven
// fastest) + LN fused into GEMM staging (per-row stats) + RoPE fused into
// qkv GEMM epilogue. No pre-split buffers, no standalone LN/rope passes.
// B=16, S=1024, T=512, D=256, H=8, DH=32, L=4, FF=1024. M = B*S = 16384.
// ---------------------------------------------------------------------------

#define M_ROWS 16384
#define D_MODEL 256
#define T_IN 512
#define FF_DIM 1024
#define N_HEADS 8
#define DH 32
#define SEQ 1024
#define N_LAYERS 4

__device__ float g_y[M_ROWS * D_MODEL];
__device__ float g_h[M_ROWS * D_MODEL];
__device__ float g_qkv[M_ROWS * 3 * D_MODEL];
__device__ float g_att[M_ROWS * D_MODEL];
__device__ float g_ff[M_ROWS * FF_DIM];
__device__ float2 g_stats[M_ROWS];       // (mean, rstd) per row
__device__ float2 g_rope[SEQ * 16];      // (cos, sin)

__device__ __forceinline__ float tf32_round(float x) {
  uint32_t u;
  asm("cvt.rna.tf32.f32 %0, %1;" : "=r"(u) : "f"(x));
  return __uint_as_float(u);
}

__device__ __forceinline__ void mma_tf32(float* d, const uint32_t* a,
                                         const uint32_t* b) {
  asm volatile(
      "mma.sync.aligned.m16n8k8.row.col.f32.tf32.tf32.f32 "
      "{%0,%1,%2,%3}, {%4,%5,%6,%7}, {%8,%9}, {%0,%1,%2,%3};\n"
      : "+f"(d[0]), "+f"(d[1]), "+f"(d[2]), "+f"(d[3])
      : "r"(a[0]), "r"(a[1]), "r"(a[2]), "r"(a[3]), "r"(b[0]), "r"(b[1]));
}

// ---------------------------------------------------------------------------
// Per-row LN stats: one warp per row (8 rows per 256-thread block).
// ---------------------------------------------------------------------------
__global__ __launch_bounds__(256) void ln_stats_kernel(
    const float* __restrict__ in, float2* __restrict__ st) {
  const int warp = threadIdx.x >> 5;
  const int lane = threadIdx.x & 31;
  const int row = blockIdx.x * 8 + warp;
  const float* p = in + (size_t)row * D_MODEL + lane * 8;
  float4 v0 = *(const float4*)p;
  float4 v1 = *(const float4*)(p + 4);
  float v[8] = {v0.x, v0.y, v0.z, v0.w, v1.x, v1.y, v1.z, v1.w};
  float s = 0.f;
#pragma unroll
  for (int i = 0; i < 8; i++) s += v[i];
#pragma unroll
  for (int o = 16; o > 0; o >>= 1) s += __shfl_xor_sync(0xffffffffu, s, o);
  float mean = s * (1.0f / 256.0f);
  float s2 = 0.f;
#pragma unroll
  for (int i = 0; i < 8; i++) {
    float d = v[i] - mean;
    s2 += d * d;
  }
#pragma unroll
  for (int o = 16; o > 0; o >>= 1) s2 += __shfl_xor_sync(0xffffffffu, s2, o);
  float var = s2 * (1.0f / 256.0f);
  if (lane == 0) st[row] = make_float2(mean, rsqrtf(var + 1e-5f));
}

// ---------------------------------------------------------------------------
// RoPE table: (cos, sin) per (s, j), j in 0..15.
// ---------------------------------------------------------------------------
__global__ __launch_bounds__(256) void rope_table_kernel(
    float2* __restrict__ tab) {
  int idx = blockIdx.x * 256 + threadIdx.x;  // SEQ*16
  int j = idx & 15;
  int s = idx >> 4;
  float inv_freq = 1.0f / powf(10000.0f, (float)j * 0.0625f);
  float c, sn;
  sincosf((float)s * inv_freq, &c, &sn);
  tab[idx] = make_float2(c, sn);
}

// ---------------------------------------------------------------------------
// 3xTF32 GEMM (R5 core): C[M,N] = op(A)[M,K] @ B[N,K]^T + bias (+RELU/+RES)
// op(A) = LN(A) per-row via stats if LNA. ROPE rotates q/k cols in epilogue.
// Block 128x128xK16, 8 warps (2x4), warp tile 64x32, mma m16n8k8.
// smem float2 pairs (k, k+4) per slice; dynamic 64KB double-buffered.
// ---------------------------------------------------------------------------
#define GEMM_SMEM_BYTES (2 * 2 * 128 * 4 * 16 * 2)

#define LN_APPLY()                                                             \
  do {                                                                         \
    if (LNA) {                                                                 \
      const float* gp = lng + k0 + lsl * 8;                                    \
      const float* bp = lnb + k0 + lsl * 8;                                    \
      float4 gg0 = *(const float4*)gp, gg1 = *(const float4*)(gp + 4);         \
      float4 bb0 = *(const float4*)bp, bb1 = *(const float4*)(bp + 4);         \
      va0.x = fmaf((va0.x - mu) * rsd, gg0.x, bb0.x);                          \
      va0.y = fmaf((va0.y - mu) * rsd, gg0.y, bb0.y);                          \
      va0.z = fmaf((va0.z - mu) * rsd, gg0.z, bb0.z);                          \
      va0.w = fmaf((va0.w - mu) * rsd, gg0.w, bb0.w);                          \
      va1.x = fmaf((va1.x - mu) * rsd, gg1.x, bb1.x);                          \
      va1.y = fmaf((va1.y - mu) * rsd, gg1.y, bb1.y);                          \
      va1.z = fmaf((va1.z - mu) * rsd, gg1.z, bb1.z);                          \
      va1.w = fmaf((va1.w - mu) * rsd, gg1.w, bb1.w);                          \
    }                                                                          \
  } while (0)

#define STAGE_STORE(BUF)                                                       \
  do {                                                                         \
    AsP[BUF][lsl][lrow][0] =                                                   \
        make_float2(tf32_round(va0.x), tf32_round(va1.x));                     \
    AsP[BUF][lsl][lrow][1] =                                                   \
        make_float2(tf32_round(va0.y), tf32_round(va1.y));                     \
    AsP[BUF][lsl][lrow][2] =                                                   \
        make_float2(tf32_round(va0.z), tf32_round(va1.z));                     \
    AsP[BUF][lsl][lrow][3] =                                                   \
        make_float2(tf32_round(va0.w), tf32_round(va1.w));                     \
    AsL[BUF][lsl][lrow][0] =                                                   \
        make_float2(tf32_round(va0.x - AsP[BUF][lsl][lrow][0].x),              \
                    tf32_round(va1.x - AsP[BUF][lsl][lrow][0].y));             \
    AsL[BUF][lsl][lrow][1] =                                                   \
        make_float2(tf32_round(va0.y - AsP[BUF][lsl][lrow][1].x),              \
                    tf32_round(va1.y - AsP[BUF][lsl][lrow][1].y));             \
    AsL[BUF][lsl][lrow][2] =                                                   \
        make_float2(tf32_round(va0.z - AsP[BUF][lsl][lrow][2].x),              \
                    tf32_round(va1.z - AsP[BUF][lsl][lrow][2].y));             \
    AsL[BUF][lsl][lrow][3] =                                                   \
        make_float2(tf32_round(va0.w - AsP[BUF][lsl][lrow][3].x),              \
                    tf32_round(va1.w - AsP[BUF][lsl][lrow][3].y));             \
    BsP[BUF][lsl][lrow][0] =                                                   \
        make_float2(tf32_round(vb0.x), tf32_round(vb1.x));                     \
    BsP[BUF][lsl][lrow][1] =                                                   \
        make_float2(tf32_round(vb0.y), tf32_round(vb1.y));                     \
    BsP[BUF][lsl][lrow][2] =                                                   \
        make_float2(tf32_round(vb0.z), tf32_round(vb1.z));                     \
    BsP[BUF][lsl][lrow][3] =                                                   \
        make_float2(tf32_round(vb0.w), tf32_round(vb1.w));                     \
    BsL[BUF][lsl][lrow][0] =                                                   \
        make_float2(tf32_round(vb0.x - BsP[BUF][lsl][lrow][0].x),              \
                    tf32_round(vb1.x - BsP[BUF][lsl][lrow][0].y));             \
    BsL[BUF][lsl][lrow][1] =                                                   \
        make_float2(tf32_round(vb0.y - BsP[BUF][lsl][lrow][1].x),              \
                    tf32_round(vb1.y - BsP[BUF][lsl][lrow][1].y));             \
    BsL[BUF][lsl][lrow][2] =                                                   \
        make_float2(tf32_round(vb0.z - BsP[BUF][lsl][lrow][2].x),              \
                    tf32_round(vb1.z - BsP[BUF][lsl][lrow][2].y));             \
    BsL[BUF][lsl][lrow][3] =                                                   \
        make_float2(tf32_round(vb0.w - BsP[BUF][lsl][lrow][3].x),              \
                    tf32_round(vb1.w - BsP[BUF][lsl][lrow][3].y));             \
  } while (0)

#define COMPUTE_STAGE(BUF)                                                     \
  _Pragma("unroll") for (int s = 0; s < 2; s++) {                              \
    uint32_t bfH[4][2], bfL[4][2];                                             \
    _Pragma("unroll") for (int nt = 0; nt < 4; nt++) {                         \
      const int rw = wn * 32 + nt * 8 + gid;                                   \
      float2 ph = BsP[BUF][s][rw][tg];                                         \
      float2 pl = BsL[BUF][s][rw][tg];                                         \
      bfH[nt][0] = __float_as_uint(ph.x); bfH[nt][1] = __float_as_uint(ph.y);  \
      bfL[nt][0] = __float_as_uint(pl.x); bfL[nt][1] = __float_as_uint(pl.y);  \
    }                                                                          \
    _Pragma("unroll") for (int mt = 0; mt < 4; mt++) {                         \
      const int rb = wm * 64 + mt * 16 + gid;                                  \
      float2 h0 = AsP[BUF][s][rb][tg];                                         \
      float2 h8 = AsP[BUF][s][rb + 8][tg];                                     \
      float2 l0 = AsL[BUF][s][rb][tg];                                         \
      float2 l8 = AsL[BUF][s][rb + 8][tg];                                     \
      uint32_t afH[4] = {__float_as_uint(h0.x), __float_as_uint(h8.x),         \
                         __float_as_uint(h0.y), __float_as_uint(h8.y)};        \
      uint32_t afL[4] = {__float_as_uint(l0.x), __float_as_uint(l8.x),         \
                         __float_as_uint(l0.y), __float_as_uint(l8.y)};        \
      _Pragma("unroll") for (int nt = 0; nt < 4; nt++) {                       \
        mma_tf32(acc[mt][nt], afH, bfH[nt]);                                   \
        mma_tf32(acc[mt][nt], afH, bfL[nt]);                                   \
        mma_tf32(acc[mt][nt], afL, bfH[nt]);                                   \
      }                                                                        \
    }                                                                          \
  }

template <bool LNA, bool RELU, bool RES, bool ROPE>
__global__ __launch_bounds__(256, 2) void gemm_kernel(
    const float* __restrict__ A, const float* __restrict__ B,
    const float* __restrict__ bias, const float* __restrict__ res,
    const float2* __restrict__ stats, const float* __restrict__ lng,
    const float* __restrict__ lnb, const float2* __restrict__ rope,
    float* __restrict__ C, int M, int N, int K) {
  extern __shared__ float2 smem_dyn[];
  // [buf][slice][row][c]: pair (v(k=s*8+c), v(k=s*8+c+4))
  typedef float2 (*SmemT)[2][128][4];
  SmemT AsP = (SmemT)smem_dyn;
  SmemT AsL = (SmemT)(smem_dyn + 2 * 2 * 128 * 4);
  SmemT BsP = (SmemT)(smem_dyn + 2 * 2 * 128 * 4 * 2);
  SmemT BsL = (SmemT)(smem_dyn + 2 * 2 * 128 * 4 * 3);

  const int tid = threadIdx.x;
  const int lane = tid & 31;
  const int warp = tid >> 5;
  const int wm = warp >> 2;
  const int wn = warp & 3;
  const int gid = lane >> 2;
  const int tg = lane & 3;

  const int m0 = blockIdx.y * 128;
  const int n0 = blockIdx.x * 128;

  const int lrow = tid >> 1;
  const int lsl = tid & 1;

  const float* Ap = A + (size_t)(m0 + lrow) * K + lsl * 8;
  const float* Bp = B + (size_t)(n0 + lrow) * K + lsl * 8;

  float mu = 0.f, rsd = 1.f;
  if (LNA) {
    float2 st = stats[m0 + lrow];
    mu = st.x;
    rsd = st.y;
  }

  float acc[4][4][4];
#pragma unroll
  for (int i = 0; i < 4; i++)
#pragma unroll
    for (int j = 0; j < 4; j++)
#pragma unroll
      for (int r = 0; r < 4; r++) acc[i][j][r] = 0.f;

  {
    const int k0 = 0;
    float4 va0 = *(const float4*)(Ap);
    float4 va1 = *(const float4*)(Ap + 4);
    float4 vb0 = *(const float4*)(Bp);
    float4 vb1 = *(const float4*)(Bp + 4);
    LN_APPLY();
    STAGE_STORE(0);
    (void)k0;
  }
  __syncthreads();

  int buf = 0;
  for (int k0 = 16; k0 < K; k0 += 16) {
    float4 va0 = *(const float4*)(Ap + k0);
    float4 va1 = *(const float4*)(Ap + k0 + 4);
    float4 vb0 = *(const float4*)(Bp + k0);
    float4 vb1 = *(const float4*)(Bp + k0 + 4);
    LN_APPLY();
    COMPUTE_STAGE(buf);
    const int nxt = buf ^ 1;
    STAGE_STORE(nxt);
    __syncthreads();
    buf = nxt;
  }
  COMPUTE_STAGE(buf);

  const bool doRot = ROPE && (n0 + wn * 32) < 2 * D_MODEL;

#pragma unroll
  for (int mt = 0; mt < 4; mt++) {
    const int row = m0 + wm * 64 + mt * 16 + gid;
    // rr[nt]: x=(row,col) y=(row,col+1) z=(row+8,col) w=(row+8,col+1)
    float4 rr[4];
#pragma unroll
    for (int nt = 0; nt < 4; nt++) {
      const int col = n0 + wn * 32 + nt * 8 + tg * 2;
      float2 bb = *(const float2*)&bias[col];
      rr[nt] = make_float4(acc[mt][nt][0] + bb.x, acc[mt][nt][1] + bb.y,
                           acc[mt][nt][2] + bb.x, acc[mt][nt][3] + bb.y);
    }
    if (doRot) {
      const int s = row & (SEQ - 1);
      const int s8 = s + 8;
#pragma unroll
      for (int p = 0; p < 2; p++) {
        const int j0 = p * 8 + tg * 2;
        float2 c0 = rope[s * 16 + j0];
        float2 c1 = rope[s * 16 + j0 + 1];
        float2 d0 = rope[s8 * 16 + j0];
        float2 d1 = rope[s8 * 16 + j0 + 1];
        float4 a = rr[p], q = rr[p + 2];
        rr[p].x = a.x * c0.x - q.x * c0.y;
        rr[p + 2].x = q.x * c0.x + a.x * c0.y;
        rr[p].y = a.y * c1.x - q.y * c1.y;
        rr[p + 2].y = q.y * c1.x + a.y * c1.y;
        rr[p].z = a.z * d0.x - q.z * d0.y;
        rr[p + 2].z = q.z * d0.x + a.z * d0.y;
        rr[p].w = a.w * d1.x - q.w * d1.y;
        rr[p + 2].w = q.w * d1.x + a.w * d1.y;
      }
    }
#pragma unroll
    for (int nt = 0; nt < 4; nt++) {
      const int col = n0 + wn * 32 + nt * 8 + tg * 2;
      float2 r0 = make_float2(rr[nt].x, rr[nt].y);
      float2 r1 = make_float2(rr[nt].z, rr[nt].w);
      if (RELU) {
        r0.x = fmaxf(r0.x, 0.f); r0.y = fmaxf(r0.y, 0.f);
        r1.x = fmaxf(r1.x, 0.f); r1.y = fmaxf(r1.y, 0.f);
      }
      if (RES) {
        float2 q0 = *(const float2*)&res[(size_t)row * N + col];
        float2 q1 = *(const float2*)&res[(size_t)(row + 8) * N + col];
        r0.x += q0.x; r0.y += q0.y;
        r1.x += q1.x; r1.y += q1.y;
      }
      *(float2*)&C[(size_t)row * N + col] = r0;
      *(float2*)&C[(size_t)(row + 8) * N + col] = r1;
    }
  }
}

// ---------------------------------------------------------------------------
// Full LayerNorm (tokenize norm + final norm).
// ---------------------------------------------------------------------------
__global__ __launch_bounds__(256) void ln_kernel(
    const float* __restrict__ in, const float* __restrict__ g,
    const float* __restrict__ b, float* __restrict__ out) {
  const int row = blockIdx.x;
  const int t = threadIdx.x;
  float v = in[(size_t)row * D_MODEL + t];

  float s = v;
#pragma unroll
  for (int o = 16; o > 0; o >>= 1) s += __shfl_xor_sync(0xffffffffu, s, o);
  __shared__ float ws[8];
  __shared__ float ws2[8];
  if ((t & 31) == 0) ws[t >> 5] = s;
  __syncthreads();
  float mean = (ws[0] + ws[1] + ws[2] + ws[3] + ws[4] + ws[5] + ws[6] + ws[7]) *
               (1.0f / 256.0f);
  float d = v - mean;
  float s2 = d * d;
#pragma unroll
  for (int o = 16; o > 0; o >>= 1) s2 += __shfl_xor_sync(0xffffffffu, s2, o);
  if ((t & 31) == 0) ws2[t >> 5] = s2;
  __syncthreads();
  float var = (ws2[0] + ws2[1] + ws2[2] + ws2[3] + ws2[4] + ws2[5] + ws2[6] +
               ws2[7]) * (1.0f / 256.0f);
  out[(size_t)row * D_MODEL + t] = d * rsqrtf(var + 1e-5f) * g[t] + b[t];
}

// ---------------------------------------------------------------------------
// Flash attention, fp32 (R4 core, proven). Grid (S/64, B*H), 256 threads.
// ---------------------------------------------------------------------------
#define BQ 64
#define BKT 64
__global__ __launch_bounds__(256) void attn_kernel(
    const float* __restrict__ qkv, float* __restrict__ out) {
  __shared__ float Qt[DH][BQ];
  __shared__ float Kt[DH][BKT];
  __shared__ float Vs[BKT][36];
  __shared__ float Ps[BKT][68];

  const int tid = threadIdx.x;
  const int bh = blockIdx.y;
  const int b = bh >> 3;
  const int h = bh & 7;
  const int q0 = blockIdx.x * BQ;
  const float scale = 0.17677669529663687f;

  const int lr = tid & 63;
  const int lds = tid >> 6;
  const int r64 = tid >> 2;
  const int dc = (tid & 3) << 3;

  const int tx = tid & 15;
  const int ty = tid >> 4;
  const int jh = tx >> 3;
  const int dm = tx & 7;

  {
    const float* qb = qkv + (size_t)(b * SEQ + q0 + lr) * 768 + h * 32 + lds * 8;
#pragma unroll
    for (int i = 0; i < 8; i++) Qt[lds * 8 + i][lr] = qb[i] * scale;
  }

  float m_i[4], l_i[4];
#pragma unroll
  for (int i = 0; i < 4; i++) { m_i[i] = -INFINITY; l_i[i] = 0.f; }
  float O[4][4];
#pragma unroll
  for (int i = 0; i < 4; i++)
#pragma unroll
    for (int d = 0; d < 4; d++) O[i][d] = 0.f;

  for (int kt = 0; kt < SEQ / BKT; kt++) {
    const int k0 = kt * BKT;
    __syncthreads();
    {
      const float* kb =
          qkv + (size_t)(b * SEQ + k0 + lr) * 768 + 256 + h * 32 + lds * 8;
#pragma unroll
      for (int i = 0; i < 8; i++) Kt[lds * 8 + i][lr] = kb[i];
      const float* vb =
          qkv + (size_t)(b * SEQ + k0 + r64) * 768 + 512 + h * 32 + dc;
      *(float4*)&Vs[r64][dc] = *(const float4*)vb;
      *(float4*)&Vs[r64][dc + 4] = *(const float4*)(vb + 4);
    }
    __syncthreads();

    float s4[4][4];
#pragma unroll
    for (int i = 0; i < 4; i++)
#pragma unroll
      for (int j = 0; j < 4; j++) s4[i][j] = 0.f;
#pragma unroll
    for (int d = 0; d < DH; d++) {
      float4 qv = *(const float4*)&Qt[d][ty * 4];
      float4 kv = *(const float4*)&Kt[d][tx * 4];
      float qa[4] = {qv.x, qv.y, qv.z, qv.w};
      float ka[4] = {kv.x, kv.y, kv.z, kv.w};
#pragma unroll
      for (int i = 0; i < 4; i++)
#pragma unroll
        for (int j = 0; j < 4; j++) s4[i][j] = fmaf(qa[i], ka[j], s4[i][j]);
    }

    const int swz = (ty ^ (tx >> 1)) * 4;
    float cf_i[4];
#pragma unroll
    for (int i = 0; i < 4; i++) {
      float lm = fmaxf(fmaxf(s4[i][0], s4[i][1]), fmaxf(s4[i][2], s4[i][3]));
#pragma unroll
      for (int o = 8; o > 0; o >>= 1)
        lm = fmaxf(lm, __shfl_xor_sync(0xffffffffu, lm, o));
      float mn = fmaxf(m_i[i], lm);
      cf_i[i] = __expf(m_i[i] - mn);
      m_i[i] = mn;
      float ps = 0.f;
#pragma unroll
      for (int j = 0; j < 4; j++) {
        float p = __expf(s4[i][j] - mn);
        Ps[tx * 4 + j][swz + i] = p;
        ps += p;
      }
#pragma unroll
      for (int o = 8; o > 0; o >>= 1)
        ps += __shfl_xor_sync(0xffffffffu, ps, o);
      l_i[i] = l_i[i] * cf_i[i] + ps;
    }
#pragma unroll
    for (int i = 0; i < 4; i++)
#pragma unroll
      for (int d = 0; d < 4; d++) O[i][d] *= cf_i[i];
    __syncthreads();

#pragma unroll
    for (int jblk = 0; jblk < 4; jblk++) {
      const int c4 = (ty ^ ((jh * 4 + jblk) & 7)) * 4;
#pragma unroll
      for (int jj = 0; jj < 8; jj++) {
        const int j = jh * 32 + jblk * 8 + jj;
        float4 p4 = *(const float4*)&Ps[j][c4];
        float4 v4 = *(const float4*)&Vs[j][dm * 4];
        float pa[4] = {p4.x, p4.y, p4.z, p4.w};
        float va[4] = {v4.x, v4.y, v4.z, v4.w};
#pragma unroll
        for (int i = 0; i < 4; i++)
#pragma unroll
          for (int d = 0; d < 4; d++)
            O[i][d] = fmaf(pa[i], va[d], O[i][d]);
      }
    }
  }

#pragma unroll
  for (int i = 0; i < 4; i++)
#pragma unroll
    for (int d = 0; d < 4; d++)
      O[i][d] += __shfl_xor_sync(0xffffffffu, O[i][d], 8);

  if (jh == 0) {
#pragma unroll
    for (int i = 0; i < 4; i++) {
      const float inv = 1.0f / l_i[i];
      float4 r = make_float4(O[i][0] * inv, O[i][1] * inv, O[i][2] * inv,
                             O[i][3] * inv);
      *(float4*)&out[(size_t)(b * SEQ + q0 + ty * 4 + i) * D_MODEL + h * 32 +
                     dm * 4] = r;
    }
  }
}

// ---------------------------------------------------------------------------
// Launch
// ---------------------------------------------------------------------------
extern "C" void kernel_launch(void* const* d_in, const int* in_sizes, int n_in,
                              void* d_out, int out_size) {
  const float* x         = (const float*)d_in[0];
  const float* tok_w     = (const float*)d_in[1];
  const float* tok_b     = (const float*)d_in[2];
  const float* tnorm_g   = (const float*)d_in[3];
  const float* tnorm_b   = (const float*)d_in[4];
  const float* in_proj_w = (const float*)d_in[5];
  const float* in_proj_b = (const float*)d_in[6];
  const float* out_w     = (const float*)d_in[7];
  const float* out_b     = (const float*)d_in[8];
  const float* ln1_g     = (const float*)d_in[9];
  const float* ln1_b     = (const float*)d_in[10];
  const float* ln2_g     = (const float*)d_in[11];
  const float* ln2_b     = (const float*)d_in[12];
  const float* lin1_w    = (const float*)d_in[13];
  const float* lin1_b    = (const float*)d_in[14];
  const float* lin2_w    = (const float*)d_in[15];
  const float* lin2_b    = (const float*)d_in[16];
  const float* fnorm_g   = (const float*)d_in[17];
  const float* fnorm_b   = (const float*)d_in[18];
  float* out = (float*)d_out;

  float *y, *h, *qkv, *att, *ff;
  float2 *st, *rope;
  cudaGetSymbolAddress((void**)&y, g_y);
  cudaGetSymbolAddress((void**)&h, g_h);
  cudaGetSymbolAddress((void**)&qkv, g_qkv);
  cudaGetSymbolAddress((void**)&att, g_att);
  cudaGetSymbolAddress((void**)&ff, g_ff);
  cudaGetSymbolAddress((void**)&st, g_stats);
  cudaGetSymbolAddress((void**)&rope, g_rope);

  const int M = M_ROWS;
  const int SB = GEMM_SMEM_BYTES;
  cudaFuncSetAttribute(gemm_kernel<false, false, false, false>,
                       cudaFuncAttributeMaxDynamicSharedMemorySize, SB);
  cudaFuncSetAttribute(gemm_kernel<true, false, false, true>,
                       cudaFuncAttributeMaxDynamicSharedMemorySize, SB);
  cudaFuncSetAttribute(gemm_kernel<false, false, true, false>,
                       cudaFuncAttributeMaxDynamicSharedMemorySize, SB);
  cudaFuncSetAttribute(gemm_kernel<true, true, false, false>,
                       cudaFuncAttributeMaxDynamicSharedMemorySize, SB);

  dim3 blk(256);

  rope_table_kernel<<<SEQ * 16 / 256, blk>>>(rope);

  // Tokenize: y = x @ tok_w^T + tok_b ; h = LN(y)
  gemm_kernel<false, false, false, false><<<dim3(2, M / 128), blk, SB>>>(
      x, tok_w, tok_b, nullptr, nullptr, nullptr, nullptr, nullptr, y, M,
      D_MODEL, T_IN);
  ln_kernel<<<M, blk>>>(y, tnorm_g, tnorm_b, h);

  for (int i = 0; i < N_LAYERS; i++) {
    ln_stats_kernel<<<M / 8, blk>>>(h, st);
    gemm_kernel<true, false, false, true><<<dim3(6, M / 128), blk, SB>>>(
        h, in_proj_w + (size_t)i * 768 * D_MODEL, in_proj_b + i * 768, nullptr,
        st, ln1_g + i * D_MODEL, ln1_b + i * D_MODEL, rope, qkv, M, 768,
        D_MODEL);
    attn_kernel<<<dim3(SEQ / BQ, 16 * N_HEADS), blk>>>(qkv, att);
    gemm_kernel<false, false, true, false><<<dim3(2, M / 128), blk, SB>>>(
        att, out_w + (size_t)i * D_MODEL * D_MODEL, out_b + i * D_MODEL, h,
        nullptr, nullptr, nullptr, nullptr, h, M, D_MODEL, D_MODEL);
    ln_stats_kernel<<<M / 8, blk>>>(h, st);
    gemm_kernel<true, true, false, false><<<dim3(8, M / 128), blk, SB>>>(
        h, lin1_w + (size_t)i * FF_DIM * D_MODEL, lin1_b + i * FF_DIM, nullptr,
        st, ln2_g + i * D_MODEL, ln2_b + i * D_MODEL, nullptr, ff, M, FF_DIM,
        D_MODEL);
    gemm_kernel<false, false, true, false><<<dim3(2, M / 128), blk, SB>>>(
        ff, lin2_w + (size_t)i * D_MODEL * FF_DIM, lin2_b + i * D_MODEL, h,
        nullptr, nullptr, nullptr, nullptr, h, M, D_MODEL, FF_DIM);
  }

  ln_kernel<<<M, blk>>>(h, fnorm_g, fnorm_b, out);
}

// round 9
// speedup vs baseline: 1.2048x; 1.0091x over previous
#include <cuda_runtime.h>
#include <math.h>
#include <stdint.h>

// ---------------------------------------------------------------------------
// iTransformer encoder, round 9: R8 + dependency-aware mma issue order
// (term-major: all HH, then HL, then LH -> 8 independent accs between
// same-acc reuses; per-acc order unchanged => bit-identical results).
// B=16, S=1024, T=512, D=256, H=8, DH=32, L=4, FF=1024. M = B*S = 16384.
// ---------------------------------------------------------------------------

#define M_ROWS 16384
#define D_MODEL 256
#define T_IN 512
#define FF_DIM 1024
#define N_HEADS 8
#define DH 32
#define SEQ 1024
#define N_LAYERS 4

__device__ float g_y[M_ROWS * D_MODEL];
__device__ float g_h[M_ROWS * D_MODEL];
__device__ float g_qkv[M_ROWS * 3 * D_MODEL];
__device__ float g_att[M_ROWS * D_MODEL];
__device__ float g_ff[M_ROWS * FF_DIM];
__device__ float2 g_stats[M_ROWS];       // (mean, rstd) per row
__device__ float2 g_rope[SEQ * 16];      // (cos, sin)

__device__ __forceinline__ float tf32_round(float x) {
  uint32_t u;
  asm("cvt.rna.tf32.f32 %0, %1;" : "=r"(u) : "f"(x));
  return __uint_as_float(u);
}

// NOT volatile: pure register op; lets ptxas pipeline around it.
__device__ __forceinline__ void mma_tf32(float* d, const uint32_t* a,
                                         const uint32_t* b) {
  asm("mma.sync.aligned.m16n8k8.row.col.f32.tf32.tf32.f32 "
      "{%0,%1,%2,%3}, {%4,%5,%6,%7}, {%8,%9}, {%0,%1,%2,%3};\n"
      : "+f"(d[0]), "+f"(d[1]), "+f"(d[2]), "+f"(d[3])
      : "r"(a[0]), "r"(a[1]), "r"(a[2]), "r"(a[3]), "r"(b[0]), "r"(b[1]));
}

// ---------------------------------------------------------------------------
// Per-row LN stats: one warp per row (8 rows per 256-thread block).
// ---------------------------------------------------------------------------
__global__ __launch_bounds__(256) void ln_stats_kernel(
    const float* __restrict__ in, float2* __restrict__ st) {
  const int warp = threadIdx.x >> 5;
  const int lane = threadIdx.x & 31;
  const int row = blockIdx.x * 8 + warp;
  const float* p = in + (size_t)row * D_MODEL + lane * 8;
  float4 v0 = *(const float4*)p;
  float4 v1 = *(const float4*)(p + 4);
  float v[8] = {v0.x, v0.y, v0.z, v0.w, v1.x, v1.y, v1.z, v1.w};
  float s = 0.f;
#pragma unroll
  for (int i = 0; i < 8; i++) s += v[i];
#pragma unroll
  for (int o = 16; o > 0; o >>= 1) s += __shfl_xor_sync(0xffffffffu, s, o);
  float mean = s * (1.0f / 256.0f);
  float s2 = 0.f;
#pragma unroll
  for (int i = 0; i < 8; i++) {
    float d = v[i] - mean;
    s2 += d * d;
  }
#pragma unroll
  for (int o = 16; o > 0; o >>= 1) s2 += __shfl_xor_sync(0xffffffffu, s2, o);
  float var = s2 * (1.0f / 256.0f);
  if (lane == 0) st[row] = make_float2(mean, rsqrtf(var + 1e-5f));
}

// ---------------------------------------------------------------------------
// RoPE table: (cos, sin) per (s, j), j in 0..15.
// ---------------------------------------------------------------------------
__global__ __launch_bounds__(256) void rope_table_kernel(
    float2* __restrict__ tab) {
  int idx = blockIdx.x * 256 + threadIdx.x;  // SEQ*16
  int j = idx & 15;
  int s = idx >> 4;
  float inv_freq = 1.0f / powf(10000.0f, (float)j * 0.0625f);
  float c, sn;
  sincosf((float)s * inv_freq, &c, &sn);
  tab[idx] = make_float2(c, sn);
}

// ---------------------------------------------------------------------------
// 3xTF32 GEMM: C[M,N] = op(A)[M,K] @ B[N,K]^T + bias (+RELU/+RES)
// op(A) = LN(A) per-row via stats if LNA. ROPE rotates q/k cols in epilogue.
// Block 128x128xK16, 8 warps (2x4), warp tile 64x32, mma m16n8k8.
// ---------------------------------------------------------------------------
#define GEMM_SMEM_BYTES (2 * 2 * 128 * 4 * 16 * 2)

#define LN_APPLY()                                                             \
  do {                                                                         \
    if (LNA) {                                                                 \
      const float* gp = lng + k0 + lsl * 8;                                    \
      const float* bp = lnb + k0 + lsl * 8;                                    \
      float4 gg0 = *(const float4*)gp, gg1 = *(const float4*)(gp + 4);         \
      float4 bb0 = *(const float4*)bp, bb1 = *(const float4*)(bp + 4);         \
      va0.x = fmaf((va0.x - mu) * rsd, gg0.x, bb0.x);                          \
      va0.y = fmaf((va0.y - mu) * rsd, gg0.y, bb0.y);                          \
      va0.z = fmaf((va0.z - mu) * rsd, gg0.z, bb0.z);                          \
      va0.w = fmaf((va0.w - mu) * rsd, gg0.w, bb0.w);                          \
      va1.x = fmaf((va1.x - mu) * rsd, gg1.x, bb1.x);                          \
      va1.y = fmaf((va1.y - mu) * rsd, gg1.y, bb1.y);                          \
      va1.z = fmaf((va1.z - mu) * rsd, gg1.z, bb1.z);                          \
      va1.w = fmaf((va1.w - mu) * rsd, gg1.w, bb1.w);                          \
    }                                                                          \
  } while (0)

#define STAGE_STORE(BUF)                                                       \
  do {                                                                         \
    float2 h0 = make_float2(tf32_round(va0.x), tf32_round(va1.x));             \
    float2 h1 = make_float2(tf32_round(va0.y), tf32_round(va1.y));             \
    float2 h2 = make_float2(tf32_round(va0.z), tf32_round(va1.z));             \
    float2 h3 = make_float2(tf32_round(va0.w), tf32_round(va1.w));             \
    AsP[BUF][lsl][lrow][0] = h0;                                               \
    AsP[BUF][lsl][lrow][1] = h1;                                               \
    AsP[BUF][lsl][lrow][2] = h2;                                               \
    AsP[BUF][lsl][lrow][3] = h3;                                               \
    AsL[BUF][lsl][lrow][0] = make_float2(tf32_round(va0.x - h0.x),             \
                                         tf32_round(va1.x - h0.y));            \
    AsL[BUF][lsl][lrow][1] = make_float2(tf32_round(va0.y - h1.x),             \
                                         tf32_round(va1.y - h1.y));            \
    AsL[BUF][lsl][lrow][2] = make_float2(tf32_round(va0.z - h2.x),             \
                                         tf32_round(va1.z - h2.y));            \
    AsL[BUF][lsl][lrow][3] = make_float2(tf32_round(va0.w - h3.x),             \
                                         tf32_round(va1.w - h3.y));            \
    float2 g0 = make_float2(tf32_round(vb0.x), tf32_round(vb1.x));             \
    float2 g1 = make_float2(tf32_round(vb0.y), tf32_round(vb1.y));             \
    float2 g2 = make_float2(tf32_round(vb0.z), tf32_round(vb1.z));             \
    float2 g3 = make_float2(tf32_round(vb0.w), tf32_round(vb1.w));             \
    BsP[BUF][lsl][lrow][0] = g0;                                               \
    BsP[BUF][lsl][lrow][1] = g1;                                               \
    BsP[BUF][lsl][lrow][2] = g2;                                               \
    BsP[BUF][lsl][lrow][3] = g3;                                               \
    BsL[BUF][lsl][lrow][0] = make_float2(tf32_round(vb0.x - g0.x),             \
                                         tf32_round(vb1.x - g0.y));            \
    BsL[BUF][lsl][lrow][1] = make_float2(tf32_round(vb0.y - g1.x),             \
                                         tf32_round(vb1.y - g1.y));            \
    BsL[BUF][lsl][lrow][2] = make_float2(tf32_round(vb0.z - g2.x),             \
                                         tf32_round(vb1.z - g2.y));            \
    BsL[BUF][lsl][lrow][3] = make_float2(tf32_round(vb0.w - g3.x),             \
                                         tf32_round(vb1.w - g3.y));            \
  } while (0)

// Term-major mma issue: HH (8 indep accs), HL, LH. Per-acc order preserved.
#define COMPUTE_STAGE(BUF)                                                     \
  _Pragma("unroll") for (int s = 0; s < 2; s++) {                              \
    uint32_t bfH[4][2], bfL[4][2];                                             \
    _Pragma("unroll") for (int nt = 0; nt < 4; nt++) {                         \
      const int rw = wn * 32 + nt * 8 + gid;                                   \
      float2 ph = BsP[BUF][s][rw][tg];                                         \
      float2 pl = BsL[BUF][s][rw][tg];                                         \
      bfH[nt][0] = __float_as_uint(ph.x); bfH[nt][1] = __float_as_uint(ph.y);  \
      bfL[nt][0] = __float_as_uint(pl.x); bfL[nt][1] = __float_as_uint(pl.y);  \
    }                                                                          \
    _Pragma("unroll") for (int mh = 0; mh < 2; mh++) {                         \
      uint32_t afH[2][4], afL[2][4];                                           \
      _Pragma("unroll") for (int mi = 0; mi < 2; mi++) {                       \
        const int rb = wm * 64 + (mh * 2 + mi) * 16 + gid;                     \
        float2 ah0 = AsP[BUF][s][rb][tg];                                      \
        float2 ah8 = AsP[BUF][s][rb + 8][tg];                                  \
        float2 al0 = AsL[BUF][s][rb][tg];                                      \
        float2 al8 = AsL[BUF][s][rb + 8][tg];                                  \
        afH[mi][0] = __float_as_uint(ah0.x);                                   \
        afH[mi][1] = __float_as_uint(ah8.x);                                   \
        afH[mi][2] = __float_as_uint(ah0.y);                                   \
        afH[mi][3] = __float_as_uint(ah8.y);                                   \
        afL[mi][0] = __float_as_uint(al0.x);                                   \
        afL[mi][1] = __float_as_uint(al8.x);                                   \
        afL[mi][2] = __float_as_uint(al0.y);                                   \
        afL[mi][3] = __float_as_uint(al8.y);                                   \
      }                                                                        \
      _Pragma("unroll") for (int mi = 0; mi < 2; mi++)                         \
          _Pragma("unroll") for (int nt = 0; nt < 4; nt++)                     \
          mma_tf32(acc[mh * 2 + mi][nt], afH[mi], bfH[nt]);                    \
      _Pragma("unroll") for (int mi = 0; mi < 2; mi++)                         \
          _Pragma("unroll") for (int nt = 0; nt < 4; nt++)                     \
          mma_tf32(acc[mh * 2 + mi][nt], afH[mi], bfL[nt]);                    \
      _Pragma("unroll") for (int mi = 0; mi < 2; mi++)                         \
          _Pragma("unroll") for (int nt = 0; nt < 4; nt++)                     \
          mma_tf32(acc[mh * 2 + mi][nt], afL[mi], bfH[nt]);                    \
    }                                                                          \
  }

template <bool LNA, bool RELU, bool RES, bool ROPE>
__global__ __launch_bounds__(256, 2) void gemm_kernel(
    const float* __restrict__ A, const float* __restrict__ B,
    const float* __restrict__ bias, const float* __restrict__ res,
    const float2* __restrict__ stats, const float* __restrict__ lng,
    const float* __restrict__ lnb, const float2* __restrict__ rope,
    float* __restrict__ C, int M, int N, int K) {
  extern __shared__ float2 smem_dyn[];
  typedef float2 (*SmemT)[2][128][4];
  SmemT AsP = (SmemT)smem_dyn;
  SmemT AsL = (SmemT)(smem_dyn + 2 * 2 * 128 * 4);
  SmemT BsP = (SmemT)(smem_dyn + 2 * 2 * 128 * 4 * 2);
  SmemT BsL = (SmemT)(smem_dyn + 2 * 2 * 128 * 4 * 3);

  const int tid = threadIdx.x;
  const int lane = tid & 31;
  const int warp = tid >> 5;
  const int wm = warp >> 2;
  const int wn = warp & 3;
  const int gid = lane >> 2;
  const int tg = lane & 3;

  const int m0 = blockIdx.y * 128;
  const int n0 = blockIdx.x * 128;

  const int lrow = tid >> 1;
  const int lsl = tid & 1;

  const float* Ap = A + (size_t)(m0 + lrow) * K + lsl * 8;
  const float* Bp = B + (size_t)(n0 + lrow) * K + lsl * 8;

  float mu = 0.f, rsd = 1.f;
  if (LNA) {
    float2 st = stats[m0 + lrow];
    mu = st.x;
    rsd = st.y;
  }

  float acc[4][4][4];
#pragma unroll
  for (int i = 0; i < 4; i++)
#pragma unroll
    for (int j = 0; j < 4; j++)
#pragma unroll
      for (int r = 0; r < 4; r++) acc[i][j][r] = 0.f;

  {
    const int k0 = 0;
    float4 va0 = *(const float4*)(Ap);
    float4 va1 = *(const float4*)(Ap + 4);
    float4 vb0 = *(const float4*)(Bp);
    float4 vb1 = *(const float4*)(Bp + 4);
    LN_APPLY();
    STAGE_STORE(0);
    (void)k0;
  }
  __syncthreads();

  int buf = 0;
  for (int k0 = 16; k0 < K; k0 += 16) {
    float4 va0 = *(const float4*)(Ap + k0);
    float4 va1 = *(const float4*)(Ap + k0 + 4);
    float4 vb0 = *(const float4*)(Bp + k0);
    float4 vb1 = *(const float4*)(Bp + k0 + 4);
    LN_APPLY();
    COMPUTE_STAGE(buf);
    const int nxt = buf ^ 1;
    STAGE_STORE(nxt);
    __syncthreads();
    buf = nxt;
  }
  COMPUTE_STAGE(buf);

  const bool doRot = ROPE && (n0 + wn * 32) < 2 * D_MODEL;

#pragma unroll
  for (int mt = 0; mt < 4; mt++) {
    const int row = m0 + wm * 64 + mt * 16 + gid;
    float4 rr[4];
#pragma unroll
    for (int nt = 0; nt < 4; nt++) {
      const int col = n0 + wn * 32 + nt * 8 + tg * 2;
      float2 bb = *(const float2*)&bias[col];
      rr[nt] = make_float4(acc[mt][nt][0] + bb.x, acc[mt][nt][1] + bb.y,
                           acc[mt][nt][2] + bb.x, acc[mt][nt][3] + bb.y);
    }
    if (doRot) {
      const int s = row & (SEQ - 1);
      const int s8 = s + 8;
#pragma unroll
      for (int p = 0; p < 2; p++) {
        const int j0 = p * 8 + tg * 2;
        float2 c0 = rope[s * 16 + j0];
        float2 c1 = rope[s * 16 + j0 + 1];
        float2 d0 = rope[s8 * 16 + j0];
        float2 d1 = rope[s8 * 16 + j0 + 1];
        float4 a = rr[p], q = rr[p + 2];
        rr[p].x = a.x * c0.x - q.x * c0.y;
        rr[p + 2].x = q.x * c0.x + a.x * c0.y;
        rr[p].y = a.y * c1.x - q.y * c1.y;
        rr[p + 2].y = q.y * c1.x + a.y * c1.y;
        rr[p].z = a.z * d0.x - q.z * d0.y;
        rr[p + 2].z = q.z * d0.x + a.z * d0.y;
        rr[p].w = a.w * d1.x - q.w * d1.y;
        rr[p + 2].w = q.w * d1.x + a.w * d1.y;
      }
    }
#pragma unroll
    for (int nt = 0; nt < 4; nt++) {
      const int col = n0 + wn * 32 + nt * 8 + tg * 2;
      float2 r0 = make_float2(rr[nt].x, rr[nt].y);
      float2 r1 = make_float2(rr[nt].z, rr[nt].w);
      if (RELU) {
        r0.x = fmaxf(r0.x, 0.f); r0.y = fmaxf(r0.y, 0.f);
        r1.x = fmaxf(r1.x, 0.f); r1.y = fmaxf(r1.y, 0.f);
      }
      if (RES) {
        float2 q0 = *(const float2*)&res[(size_t)row * N + col];
        float2 q1 = *(const float2*)&res[(size_t)(row + 8) * N + col];
        r0.x += q0.x; r0.y += q0.y;
        r1.x += q1.x; r1.y += q1.y;
      }
      *(float2*)&C[(size_t)row * N + col] = r0;
      *(float2*)&C[(size_t)(row + 8) * N + col] = r1;
    }
  }
}

// ---------------------------------------------------------------------------
// Full LayerNorm (tokenize norm + final norm).
// ---------------------------------------------------------------------------
__global__ __launch_bounds__(256) void ln_kernel(
    const float* __restrict__ in, const float* __restrict__ g,
    const float* __restrict__ b, float* __restrict__ out) {
  const int row = blockIdx.x;
  const int t = threadIdx.x;
  float v = in[(size_t)row * D_MODEL + t];

  float s = v;
#pragma unroll
  for (int o = 16; o > 0; o >>= 1) s += __shfl_xor_sync(0xffffffffu, s, o);
  __shared__ float ws[8];
  __shared__ float ws2[8];
  if ((t & 31) == 0) ws[t >> 5] = s;
  __syncthreads();
  float mean = (ws[0] + ws[1] + ws[2] + ws[3] + ws[4] + ws[5] + ws[6] + ws[7]) *
               (1.0f / 256.0f);
  float d = v - mean;
  float s2 = d * d;
#pragma unroll
  for (int o = 16; o > 0; o >>= 1) s2 += __shfl_xor_sync(0xffffffffu, s2, o);
  if ((t & 31) == 0) ws2[t >> 5] = s2;
  __syncthreads();
  float var = (ws2[0] + ws2[1] + ws2[2] + ws2[3] + ws2[4] + ws2[5] + ws2[6] +
               ws2[7]) * (1.0f / 256.0f);
  out[(size_t)row * D_MODEL + t] = d * rsqrtf(var + 1e-5f) * g[t] + b[t];
}

// ---------------------------------------------------------------------------
// Flash attention, fp32 (R4 core, proven). Grid (S/64, B*H), 256 threads.
// ---------------------------------------------------------------------------
#define BQ 64
#define BKT 64
__global__ __launch_bounds__(256) void attn_kernel(
    const float* __restrict__ qkv, float* __restrict__ out) {
  __shared__ float Qt[DH][BQ];
  __shared__ float Kt[DH][BKT];
  __shared__ float Vs[BKT][36];
  __shared__ float Ps[BKT][68];

  const int tid = threadIdx.x;
  const int bh = blockIdx.y;
  const int b = bh >> 3;
  const int h = bh & 7;
  const int q0 = blockIdx.x * BQ;
  const float scale = 0.17677669529663687f;

  const int lr = tid & 63;
  const int lds = tid >> 6;
  const int r64 = tid >> 2;
  const int dc = (tid & 3) << 3;

  const int tx = tid & 15;
  const int ty = tid >> 4;
  const int jh = tx >> 3;
  const int dm = tx & 7;

  {
    const float* qb = qkv + (size_t)(b * SEQ + q0 + lr) * 768 + h * 32 + lds * 8;
#pragma unroll
    for (int i = 0; i < 8; i++) Qt[lds * 8 + i][lr] = qb[i] * scale;
  }

  float m_i[4], l_i[4];
#pragma unroll
  for (int i = 0; i < 4; i++) { m_i[i] = -INFINITY; l_i[i] = 0.f; }
  float O[4][4];
#pragma unroll
  for (int i = 0; i < 4; i++)
#pragma unroll
    for (int d = 0; d < 4; d++) O[i][d] = 0.f;

  for (int kt = 0; kt < SEQ / BKT; kt++) {
    const int k0 = kt * BKT;
    __syncthreads();
    {
      const float* kb =
          qkv + (size_t)(b * SEQ + k0 + lr) * 768 + 256 + h * 32 + lds * 8;
#pragma unroll
      for (int i = 0; i < 8; i++) Kt[lds * 8 + i][lr] = kb[i];
      const float* vb =
          qkv + (size_t)(b * SEQ + k0 + r64) * 768 + 512 + h * 32 + dc;
      *(float4*)&Vs[r64][dc] = *(const float4*)vb;
      *(float4*)&Vs[r64][dc + 4] = *(const float4*)(vb + 4);
    }
    __syncthreads();

    float s4[4][4];
#pragma unroll
    for (int i = 0; i < 4; i++)
#pragma unroll
      for (int j = 0; j < 4; j++) s4[i][j] = 0.f;
#pragma unroll
    for (int d = 0; d < DH; d++) {
      float4 qv = *(const float4*)&Qt[d][ty * 4];
      float4 kv = *(const float4*)&Kt[d][tx * 4];
      float qa[4] = {qv.x, qv.y, qv.z, qv.w};
      float ka[4] = {kv.x, kv.y, kv.z, kv.w};
#pragma unroll
      for (int i = 0; i < 4; i++)
#pragma unroll
        for (int j = 0; j < 4; j++) s4[i][j] = fmaf(qa[i], ka[j], s4[i][j]);
    }

    const int swz = (ty ^ (tx >> 1)) * 4;
    float cf_i[4];
#pragma unroll
    for (int i = 0; i < 4; i++) {
      float lm = fmaxf(fmaxf(s4[i][0], s4[i][1]), fmaxf(s4[i][2], s4[i][3]));
#pragma unroll
      for (int o = 8; o > 0; o >>= 1)
        lm = fmaxf(lm, __shfl_xor_sync(0xffffffffu, lm, o));
      float mn = fmaxf(m_i[i], lm);
      cf_i[i] = __expf(m_i[i] - mn);
      m_i[i] = mn;
      float ps = 0.f;
#pragma unroll
      for (int j = 0; j < 4; j++) {
        float p = __expf(s4[i][j] - mn);
        Ps[tx * 4 + j][swz + i] = p;
        ps += p;
      }
#pragma unroll
      for (int o = 8; o > 0; o >>= 1)
        ps += __shfl_xor_sync(0xffffffffu, ps, o);
      l_i[i] = l_i[i] * cf_i[i] + ps;
    }
#pragma unroll
    for (int i = 0; i < 4; i++)
#pragma unroll
      for (int d = 0; d < 4; d++) O[i][d] *= cf_i[i];
    __syncthreads();

#pragma unroll
    for (int jblk = 0; jblk < 4; jblk++) {
      const int c4 = (ty ^ ((jh * 4 + jblk) & 7)) * 4;
#pragma unroll
      for (int jj = 0; jj < 8; jj++) {
        const int j = jh * 32 + jblk * 8 + jj;
        float4 p4 = *(const float4*)&Ps[j][c4];
        float4 v4 = *(const float4*)&Vs[j][dm * 4];
        float pa[4] = {p4.x, p4.y, p4.z, p4.w};
        float va[4] = {v4.x, v4.y, v4.z, v4.w};
#pragma unroll
        for (int i = 0; i < 4; i++)
#pragma unroll
          for (int d = 0; d < 4; d++)
            O[i][d] = fmaf(pa[i], va[d], O[i][d]);
      }
    }
  }

#pragma unroll
  for (int i = 0; i < 4; i++)
#pragma unroll
    for (int d = 0; d < 4; d++)
      O[i][d] += __shfl_xor_sync(0xffffffffu, O[i][d], 8);

  if (jh == 0) {
#pragma unroll
    for (int i = 0; i < 4; i++) {
      const float inv = 1.0f / l_i[i];
      float4 r = make_float4(O[i][0] * inv, O[i][1] * inv, O[i][2] * inv,
                             O[i][3] * inv);
      *(float4*)&out[(size_t)(b * SEQ + q0 + ty * 4 + i) * D_MODEL + h * 32 +
                     dm * 4] = r;
    }
  }
}

// ---------------------------------------------------------------------------
// Launch
// ---------------------------------------------------------------------------
extern "C" void kernel_launch(void* const* d_in, const int* in_sizes, int n_in,
                              void* d_out, int out_size) {
  const float* x         = (const float*)d_in[0];
  const float* tok_w     = (const float*)d_in[1];
  const float* tok_b     = (const float*)d_in[2];
  const float* tnorm_g   = (const float*)d_in[3];
  const float* tnorm_b   = (const float*)d_in[4];
  const float* in_proj_w = (const float*)d_in[5];
  const float* in_proj_b = (const float*)d_in[6];
  const float* out_w     = (const float*)d_in[7];
  const float* out_b     = (const float*)d_in[8];
  const float* ln1_g     = (const float*)d_in[9];
  const float* ln1_b     = (const float*)d_in[10];
  const float* ln2_g     = (const float*)d_in[11];
  const float* ln2_b     = (const float*)d_in[12];
  const float* lin1_w    = (const float*)d_in[13];
  const float* lin1_b    = (const float*)d_in[14];
  const float* lin2_w    = (const float*)d_in[15];
  const float* lin2_b    = (const float*)d_in[16];
  const float* fnorm_g   = (const float*)d_in[17];
  const float* fnorm_b   = (const float*)d_in[18];
  float* out = (float*)d_out;

  float *y, *h, *qkv, *att, *ff;
  float2 *st, *rope;
  cudaGetSymbolAddress((void**)&y, g_y);
  cudaGetSymbolAddress((void**)&h, g_h);
  cudaGetSymbolAddress((void**)&qkv, g_qkv);
  cudaGetSymbolAddress((void**)&att, g_att);
  cudaGetSymbolAddress((void**)&ff, g_ff);
  cudaGetSymbolAddress((void**)&st, g_stats);
  cudaGetSymbolAddress((void**)&rope, g_rope);

  const int M = M_ROWS;
  const int SB = GEMM_SMEM_BYTES;
  cudaFuncSetAttribute(gemm_kernel<false, false, false, false>,
                       cudaFuncAttributeMaxDynamicSharedMemorySize, SB);
  cudaFuncSetAttribute(gemm_kernel<true, false, false, true>,
                       cudaFuncAttributeMaxDynamicSharedMemorySize, SB);
  cudaFuncSetAttribute(gemm_kernel<false, false, true, false>,
                       cudaFuncAttributeMaxDynamicSharedMemorySize, SB);
  cudaFuncSetAttribute(gemm_kernel<true, true, false, false>,
                       cudaFuncAttributeMaxDynamicSharedMemorySize, SB);

  dim3 blk(256);

  rope_table_kernel<<<SEQ * 16 / 256, blk>>>(rope);

  gemm_kernel<false, false, false, false><<<dim3(2, M / 128), blk, SB>>>(
      x, tok_w, tok_b, nullptr, nullptr, nullptr, nullptr, nullptr, y, M,
      D_MODEL, T_IN);
  ln_kernel<<<M, blk>>>(y, tnorm_g, tnorm_b, h);

  for (int i = 0; i < N_LAYERS; i++) {
    ln_stats_kernel<<<M / 8, blk>>>(h, st);
    gemm_kernel<true, false, false, true><<<dim3(6, M / 128), blk, SB>>>(
        h, in_proj_w + (size_t)i * 768 * D_MODEL, in_proj_b + i * 768, nullptr,
        st, ln1_g + i * D_MODEL, ln1_b + i * D_MODEL, rope, qkv, M, 768,
        D_MODEL);
    attn_kernel<<<dim3(SEQ / BQ, 16 * N_HEADS), blk>>>(qkv, att);
    gemm_kernel<false, false, true, false><<<dim3(2, M / 128), blk, SB>>>(
        att, out_w + (size_t)i * D_MODEL * D_MODEL, out_b + i * D_MODEL, h,
        nullptr, nullptr, nullptr, nullptr, h, M, D_MODEL, D_MODEL);
    ln_stats_kernel<<<M / 8, blk>>>(h, st);
    gemm_kernel<true, true, false, false><<<dim3(8, M / 128), blk, SB>>>(
        h, lin1_w + (size_t)i * FF_DIM * D_MODEL, lin1_b + i * FF_DIM, nullptr,
        st, ln2_g + i * D_MODEL, ln2_b + i * D_MODEL, nullptr, ff, M, FF_DIM,
        D_MODEL);
    gemm_kernel<false, false, true, false><<<dim3(2, M / 128), blk, SB>>>(
        ff, lin2_w + (size_t)i * D_MODEL * FF_DIM, lin2_b + i * D_MODEL, h,
        nullptr, nullptr, nullptr, nullptr, h, M, D_MODEL, FF_DIM);
  }

  ln_kernel<<<M, blk>>>(h, fnorm_g, fnorm_b, out);
}